// round 10
// baseline (speedup 1.0000x reference)
#include <cuda_runtime.h>
#include <cstddef>
#include <cstdint>

#define NROWS 16384
#define INDIM 768
#define CDIM  256
#define KCODES 4096
#define NUNITS 2048      // 128 row-blocks x 16 code-groups (256 codes each)
#define VQ_GRID 148

// ---- device scratch (static: allowed; no runtime allocation) ----
__device__ float g_zqsum[NROWS * CDIM];      // running zq sum -> decoder input
__device__ float g_esq[4][KCODES];           // ||E_k||^2 per codebook
__device__ float g_ze2[NROWS];               // ||ze||^2 for current stage
__device__ float g_bestv16[16][NROWS];       // per-code-group best distance
__device__ int   g_besti16[16][NROWS];       // per-code-group best index
__device__ float g_ET[4][CDIM * KCODES];     // codebooks transposed [c][code]

// ---- packed f32x2 helpers: each lane rounds .rn independently, so each
// output keeps its single ascending-k fma chain -> bit-exact vs scalar ----
__device__ __forceinline__ void fma2(unsigned long long& d,
                                     unsigned long long a,
                                     unsigned long long b)
{
    asm("fma.rn.f32x2 %0, %1, %2, %0;" : "+l"(d) : "l"(a), "l"(b));
}
__device__ __forceinline__ unsigned long long dup2(float x)
{
    unsigned long long r;
    asm("mov.b64 %0, {%1, %1};" : "=l"(r) : "f"(x));
    return r;
}
__device__ __forceinline__ float2 unpk2(unsigned long long v)
{
    float2 r;
    asm("mov.b64 {%0, %1}, %2;" : "=f"(r.x), "=f"(r.y) : "l"(v));
    return r;
}
__device__ __forceinline__ void cp_async16(uint32_t dst_smem, const void* src)
{
    asm volatile("cp.async.cg.shared.global [%0], [%1], 16;"
                 :: "r"(dst_smem), "l"(src) : "memory");
}

// ============================================================================
// fp32 SGEMM with bias via packed f32x2: C = A @ B + bias.
// 128x128 tile, 8x8 per thread (4 f32x2 column-pairs).
// ============================================================================
__global__ __launch_bounds__(256) void sgemm_bias_kernel(
    const float* __restrict__ A, const float* __restrict__ B,
    const float* __restrict__ bias, float* __restrict__ C,
    int M, int Kd, int Nn)
{
    __shared__ __align__(16) float As[32][132];  // [kk][mm]
    __shared__ __align__(16) float Bs[32][132];  // [kk][nn]

    const int tid = threadIdx.x;
    const int tx = tid & 15;
    const int ty = tid >> 4;
    const int m0 = blockIdx.y * 128;
    const int n0 = blockIdx.x * 128;

    unsigned long long acc[8][4];
#pragma unroll
    for (int i = 0; i < 8; i++)
#pragma unroll
        for (int j = 0; j < 4; j++) acc[i][j] = 0ull;

    for (int k0 = 0; k0 < Kd; k0 += 32) {
#pragma unroll
        for (int i = 0; i < 16; i++) {
            int idx = tid + i * 256;
            int mm = idx >> 5, kk = idx & 31;
            As[kk][mm] = A[(size_t)(m0 + mm) * Kd + (k0 + kk)];
        }
#pragma unroll
        for (int i = 0; i < 16; i++) {
            int idx = tid + i * 256;
            int kk = idx >> 7, nn = idx & 127;
            Bs[kk][nn] = B[(size_t)(k0 + kk) * Nn + (n0 + nn)];
        }
        __syncthreads();

#pragma unroll
        for (int kk = 0; kk < 32; kk++) {
            float4 a0 = *(const float4*)&As[kk][ty * 4];
            float4 a1 = *(const float4*)&As[kk][64 + ty * 4];
            unsigned long long aa[8] = {dup2(a0.x), dup2(a0.y), dup2(a0.z), dup2(a0.w),
                                        dup2(a1.x), dup2(a1.y), dup2(a1.z), dup2(a1.w)};
            ulonglong2 b0 = *(const ulonglong2*)&Bs[kk][tx * 4];
            ulonglong2 b1 = *(const ulonglong2*)&Bs[kk][64 + tx * 4];
            unsigned long long bb[4] = {b0.x, b0.y, b1.x, b1.y};
#pragma unroll
            for (int i = 0; i < 8; i++)
#pragma unroll
                for (int j = 0; j < 4; j++)
                    fma2(acc[i][j], aa[i], bb[j]);
        }
        __syncthreads();
    }

#pragma unroll
    for (int i = 0; i < 8; i++) {
        int row = m0 + ((i < 4) ? (ty * 4 + i) : (64 + ty * 4 + (i - 4)));
#pragma unroll
        for (int jh = 0; jh < 2; jh++) {
            int col = n0 + (jh ? (64 + tx * 4) : (tx * 4));
            float2 p0 = unpk2(acc[i][jh * 2 + 0]);
            float2 p1 = unpk2(acc[i][jh * 2 + 1]);
            float4 v;
            v.x = __fadd_rn(p0.x, bias[col + 0]);
            v.y = __fadd_rn(p0.y, bias[col + 1]);
            v.z = __fadd_rn(p1.x, bias[col + 2]);
            v.w = __fadd_rn(p1.y, bias[col + 3]);
            *(float4*)&C[(size_t)row * Nn + col] = v;
        }
    }
}

// ============================================================================
// Tiled transpose of all 4 codebooks: E[code][c] -> g_ET[stage][c][code].
// ============================================================================
__global__ void transpose4_kernel(const float* __restrict__ E0,
                                  const float* __restrict__ E1,
                                  const float* __restrict__ E2,
                                  const float* __restrict__ E3)
{
    __shared__ float tile[32][33];
    int stage = blockIdx.z;
    const float* E = (stage == 0) ? E0 : (stage == 1) ? E1 : (stage == 2) ? E2 : E3;
    int code0 = blockIdx.x * 32;
    int c0 = blockIdx.y * 32;
    int txx = threadIdx.x, tyy = threadIdx.y;
#pragma unroll
    for (int r = 0; r < 4; r++) {
        int row = tyy + r * 8;
        tile[row][txx] = E[(size_t)(code0 + row) * CDIM + (c0 + txx)];
    }
    __syncthreads();
    float* ET = g_ET[stage];
#pragma unroll
    for (int r = 0; r < 4; r++) {
        int row = tyy + r * 8;
        ET[(size_t)(c0 + row) * KCODES + (code0 + txx)] = tile[txx][row];
    }
}

// ============================================================================
// ||E_k||^2, coalesced smem-staged, exact sequential mul+add chain.
// ============================================================================
__global__ __launch_bounds__(256) void esq4_kernel(
    const float* __restrict__ E0, const float* __restrict__ E1,
    const float* __restrict__ E2, const float* __restrict__ E3)
{
    __shared__ float s[32][257];
    int stage = blockIdx.y;
    const float* E = (stage == 0) ? E0 : (stage == 1) ? E1 : (stage == 2) ? E2 : E3;
    int row0 = blockIdx.x * 32;
    int tid = threadIdx.x;
#pragma unroll
    for (int i = 0; i < 32; i++) {
        int idx = tid + i * 256;
        int r = idx >> 8, c = idx & 255;
        s[r][c] = E[(size_t)(row0 + r) * CDIM + c];
    }
    __syncthreads();
    if (tid < 32) {
        float acc = 0.f;
#pragma unroll 8
        for (int c = 0; c < CDIM; c++) {
            float v = s[tid][c];
            acc = __fadd_rn(acc, __fmul_rn(v, v));
        }
        g_esq[stage][row0 + tid] = acc;
    }
}

// ============================================================================
// ||ze||^2, coalesced (stage 0 only; later stages fused into gather).
// ============================================================================
__global__ __launch_bounds__(256) void rownorm_kernel(const float* __restrict__ ze)
{
    __shared__ float s[32][257];
    int row0 = blockIdx.x * 32;
    int tid = threadIdx.x;
#pragma unroll
    for (int i = 0; i < 32; i++) {
        int idx = tid + i * 256;
        int r = idx >> 8, c = idx & 255;
        s[r][c] = ze[(size_t)(row0 + r) * CDIM + c];
    }
    __syncthreads();
    if (tid < 32) {
        float acc = 0.f;
#pragma unroll 8
        for (int c = 0; c < CDIM; c++) {
            float v = s[tid][c];
            acc = __fadd_rn(acc, __fmul_rn(v, v));
        }
        g_ze2[row0 + tid] = acc;
    }
}

// ============================================================================
// Fused score-GEMM + argmin, statically scheduled over 2048 fine units.
// Unit u = (row-block u>>4, code-group u&15); each of 148 CTAs processes a
// CONTIGUOUS unit range (contiguity -> persistent ze tile refilled only at
// row-block boundaries, ~2-3x per CTA). 512 threads, 8x8/thread, BN=256,
// double-buffered cp.async E tiles from pre-transposed g_ET.
// Per unit: d_k = fl( fl( Z - fl(2*s_k) ) + esq_k ), thread-local best,
// warp-shuffle butterfly min-reduce (the 32 code-lanes of a row are one
// warp), lane 0 writes g_bestv16/g_besti16. Tie-break lowest index.
// Dynamic smem: As 256x132 | Bs 2 x 32x264 = 202,752 B.
// ============================================================================
#define ASTRIDE 132
#define BSTRIDE 264
#define VQ_SMEM ((256 * ASTRIDE + 2 * 32 * BSTRIDE) * 4)

__global__ __launch_bounds__(512, 1) void vq_argmin_kernel(
    const float* __restrict__ ze,   // NROWS x CDIM
    int stage)
{
    extern __shared__ __align__(16) float sm[];
    float* As = sm;                         // [256 c][ASTRIDE]  persistent
    float* Bs = sm + 256 * ASTRIDE;         // [2][32 kk][BSTRIDE]

    const int tid = threadIdx.x;
    const int tx = tid & 31;                // code group lane 0..31
    const int ty = tid >> 5;                // warp id = row group 0..15
    const float* __restrict__ esq = g_esq[stage];
    const float* __restrict__ ET = g_ET[stage];

    const int u0 = (blockIdx.x * NUNITS) / (int)gridDim.x;
    const int u1 = ((blockIdx.x + 1) * NUNITS) / (int)gridDim.x;
    const int nch = (u1 - u0) * 8;          // 8 chunks (c0 groups) per unit

    const uint32_t bs_u32 = (uint32_t)__cvta_generic_to_shared(Bs);

    // ---- prefetch chunk 0 of unit u0 ----
    {
        const int code0 = (u0 & 15) * 256;
#pragma unroll
        for (int i = 0; i < 4; i++) {
            int idx = tid + i * 512;        // 0..2047 float4 units
            int kk = idx >> 6, c4 = idx & 63;
            cp_async16(bs_u32 + (uint32_t)(kk * BSTRIDE + c4 * 4) * 4,
                       ET + (size_t)kk * KCODES + code0 + c4 * 4);
        }
        asm volatile("cp.async.commit_group;" ::: "memory");
    }

    int cur_mb = -1;
    float zrow[8];
    unsigned long long acc[8][4];

    for (int t = 0; t < nch; t++) {
        const int u = u0 + (t >> 3);
        const int k = t & 7;
        const int mb = u >> 4;
        const int code0 = (u & 15) * 256;
        const int c0 = k * 32;
        const int m0 = mb * 128;

        asm volatile("cp.async.wait_group 0;" ::: "memory");
        __syncthreads();   // chunk t resident; all done with the other buffer

        if (mb != cur_mb) {
            // refill persistent ze tile for the new row-block
#pragma unroll 8
            for (int i = 0; i < 64; i++) {
                int idx = tid + i * 512;
                int c = idx & 255, mm = idx >> 8;
                As[c * ASTRIDE + mm] = ze[(size_t)(m0 + mm) * CDIM + c];
            }
            cur_mb = mb;
#pragma unroll
            for (int i = 0; i < 8; i++) {
                int row = (i < 4) ? (ty * 4 + i) : (64 + ty * 4 + (i - 4));
                zrow[i] = g_ze2[m0 + row];
            }
            __syncthreads();
        }

        // prefetch chunk t+1 into the other buffer
        if (t + 1 < nch) {
            const int un = u0 + ((t + 1) >> 3);
            const int kn = (t + 1) & 7;
            const int code1 = (un & 15) * 256;
            const int c01 = kn * 32;
            const uint32_t dstb = bs_u32 +
                (uint32_t)(((t + 1) & 1) * 32 * BSTRIDE) * 4;
#pragma unroll
            for (int i = 0; i < 4; i++) {
                int idx = tid + i * 512;
                int kk = idx >> 6, c4 = idx & 63;
                cp_async16(dstb + (uint32_t)(kk * BSTRIDE + c4 * 4) * 4,
                           ET + (size_t)(c01 + kk) * KCODES + code1 + c4 * 4);
            }
            asm volatile("cp.async.commit_group;" ::: "memory");
        }

        if (k == 0) {
#pragma unroll
            for (int i = 0; i < 8; i++)
#pragma unroll
                for (int j = 0; j < 4; j++) acc[i][j] = 0ull;
        }

        const float* Bp = Bs + (t & 1) * (32 * BSTRIDE);
#pragma unroll
        for (int kk = 0; kk < 32; kk++) {
            const float* ar = As + (c0 + kk) * ASTRIDE;
            const float* br = Bp + kk * BSTRIDE;
            float4 a0 = *(const float4*)&ar[ty * 4];          // broadcast
            float4 a1 = *(const float4*)&ar[64 + ty * 4];     // broadcast
            unsigned long long aa[8] = {dup2(a0.x), dup2(a0.y), dup2(a0.z), dup2(a0.w),
                                        dup2(a1.x), dup2(a1.y), dup2(a1.z), dup2(a1.w)};
            ulonglong2 b0 = *(const ulonglong2*)&br[tx * 4];
            ulonglong2 b1 = *(const ulonglong2*)&br[128 + tx * 4];
            unsigned long long bb[4] = {b0.x, b0.y, b1.x, b1.y};
#pragma unroll
            for (int i = 0; i < 8; i++)
#pragma unroll
                for (int j = 0; j < 4; j++)
                    fma2(acc[i][j], aa[i], bb[j]);
        }

        // unit complete: argmin epilogue  d = fl( fl(Z - fl(2*s)) + esq )
        if (k == 7) {
            float bestv[8];
            int   besti[8];
#pragma unroll
            for (int i = 0; i < 8; i++) { bestv[i] = 3.4e38f; besti[i] = 0; }

#pragma unroll
            for (int half = 0; half < 2; half++) {
#pragma unroll
                for (int h = 0; h < 2; h++) {
                    int j2 = half * 2 + h;
                    int col = code0 + half * 128 + tx * 4 + h * 2;
                    float eq0 = esq[col];
                    float eq1 = esq[col + 1];
#pragma unroll
                    for (int i = 0; i < 8; i++) {
                        float2 pv = unpk2(acc[i][j2]);
                        float t0 = __fmul_rn(2.0f, pv.x);
                        float v0 = __fadd_rn(__fadd_rn(zrow[i], -t0), eq0);
                        if (v0 < bestv[i]) { bestv[i] = v0; besti[i] = col; }
                        float t1v = __fmul_rn(2.0f, pv.y);
                        float v1 = __fadd_rn(__fadd_rn(zrow[i], -t1v), eq1);
                        if (v1 < bestv[i]) { bestv[i] = v1; besti[i] = col + 1; }
                    }
                }
            }

            // warp butterfly min-reduce over the 32 code lanes (one warp/row)
#pragma unroll
            for (int i = 0; i < 8; i++) {
                float v = bestv[i];
                int  ix = besti[i];
#pragma unroll
                for (int off = 16; off; off >>= 1) {
                    float ov = __shfl_xor_sync(0xffffffffu, v, off);
                    int   oi = __shfl_xor_sync(0xffffffffu, ix, off);
                    if (ov < v || (ov == v && oi < ix)) { v = ov; ix = oi; }
                }
                if (tx == 0) {
                    int row = (i < 4) ? (ty * 4 + i) : (64 + ty * 4 + (i - 4));
                    g_bestv16[u & 15][m0 + row] = v;
                    g_besti16[u & 15][m0 + row] = ix;
                }
            }
        }
    }
}

// ============================================================================
// Gather: merge 16 code-group argmins (strict < over ascending code ranges ->
// first-occurrence); zq = E[nn]; residual; nn as float; accumulate zq_sum;
// stage 3 forms straight-through decoder input. Stages 0-2 also compute the
// NEXT stage's ||ze_next||^2 with the exact sequential XLA chain.
// ============================================================================
__global__ void gather_kernel(const float* __restrict__ ze,
                              const float* __restrict__ E,
                              float* __restrict__ zq_out,
                              float* __restrict__ ze_next,   // null on stage 3
                              float* __restrict__ nn_f,
                              const float* __restrict__ ze1, // stage 3 only
                              int stage)
{
    __shared__ float buf[CDIM];
    int row = blockIdx.x;
    int c = threadIdx.x;

    float bv = g_bestv16[0][row];
    int   bi = g_besti16[0][row];
#pragma unroll
    for (int h = 1; h < 16; h++) {
        float v = g_bestv16[h][row];
        int  ix = g_besti16[h][row];
        if (v < bv) { bv = v; bi = ix; }
    }
    int idx = bi;

    float q = E[(size_t)idx * CDIM + c];
    size_t o = (size_t)row * CDIM + c;
    zq_out[o] = q;
    if (ze_next) {
        float zn = __fadd_rn(ze[o], -q);
        ze_next[o] = zn;
        buf[c] = zn;
    }
    float s = (stage == 0) ? q : __fadd_rn(g_zqsum[o], q);
    if (stage == 3) {
        float z1 = ze1[o];
        s = __fadd_rn(z1, __fadd_rn(s, -z1));   // ze1 + (zq_sum - ze1)
    }
    g_zqsum[o] = s;
    if (c == 0) nn_f[row] = (float)idx;

    if (ze_next) {
        __syncthreads();
        if (c == 0) {
            float acc = 0.f;
#pragma unroll 8
            for (int i = 0; i < CDIM; i++)
                acc = __fadd_rn(acc, __fmul_rn(buf[i], buf[i]));
            g_ze2[row] = acc;
        }
    }
}

// ============================================================================
// kernel_launch
// Output layout (float32): x_hat [N,768] | ze_1..4 [N,256] | zq_1..4 [N,256]
//                          | nn_1..4 [N]
// ============================================================================
extern "C" void kernel_launch(void* const* d_in, const int* in_sizes, int n_in,
                              void* d_out, int out_size)
{
    const float* x     = (const float*)d_in[0];
    const float* W_enc = (const float*)d_in[1];
    const float* b_enc = (const float*)d_in[2];
    const float* E[4]  = {(const float*)d_in[3], (const float*)d_in[4],
                          (const float*)d_in[5], (const float*)d_in[6]};
    const float* W_dec = (const float*)d_in[7];
    const float* b_dec = (const float*)d_in[8];

    float* out = (float*)d_out;

    const size_t NC      = (size_t)NROWS * CDIM;
    const size_t OFF_ZE  = (size_t)NROWS * INDIM;
    const size_t OFF_ZQ  = OFF_ZE + 4 * NC;
    const size_t OFF_NN  = OFF_ZQ + 4 * NC;

    float* xhat = out;
    const float* ze1 = out + OFF_ZE;

    void* zqsum_ptr = nullptr;
    cudaGetSymbolAddress(&zqsum_ptr, g_zqsum);

    cudaFuncSetAttribute(vq_argmin_kernel,
                         cudaFuncAttributeMaxDynamicSharedMemorySize, VQ_SMEM);

    // codebook preprocessing: norms + transposes (one-time)
    esq4_kernel<<<dim3(KCODES / 32, 4), 256>>>(E[0], E[1], E[2], E[3]);
    transpose4_kernel<<<dim3(KCODES / 32, CDIM / 32, 4), dim3(32, 8)>>>(
        E[0], E[1], E[2], E[3]);

    // encoder: ze_1 = x @ W_enc + b_enc
    sgemm_bias_kernel<<<dim3(CDIM / 128, NROWS / 128), 256>>>(
        x, W_enc, b_enc, out + OFF_ZE, NROWS, INDIM, CDIM);

    // ||ze_1||^2 (later stages' norms are fused into gather)
    rownorm_kernel<<<NROWS / 32, 256>>>(out + OFF_ZE);

    // 4 sequential VQ stages
    for (int s = 0; s < 4; s++) {
        const float* zes = out + OFF_ZE + (size_t)s * NC;
        vq_argmin_kernel<<<VQ_GRID, 512, VQ_SMEM>>>(zes, s);
        float* zenext = (s < 3) ? (out + OFF_ZE + (size_t)(s + 1) * NC) : nullptr;
        gather_kernel<<<NROWS, 256>>>(zes, E[s],
                                      out + OFF_ZQ + (size_t)s * NC,
                                      zenext,
                                      out + OFF_NN + (size_t)s * NROWS,
                                      ze1, s);
    }

    // decoder: x_hat = decoder_input @ W_dec + b_dec
    sgemm_bias_kernel<<<dim3(INDIM / 128, NROWS / 128), 256>>>(
        (const float*)zqsum_ptr, W_dec, b_dec, xhat, NROWS, CDIM, INDIM);
}

// round 11
// speedup vs baseline: 1.8435x; 1.8435x over previous
#include <cuda_runtime.h>
#include <cuda_bf16.h>
#include <cstddef>
#include <cstdint>

#define NROWS 16384
#define INDIM 768
#define CDIM  256
#define KCODES 4096
#define BAND  8e-3f

typedef unsigned long long ull;

// ---- device scratch ----
__device__ float g_zqsum[NROWS * CDIM];
__device__ float g_esq[4][KCODES];
__device__ float g_ze2[NROWS];
__device__ float g_p1v1[NROWS];              // pass1 best approx distance
__device__ float g_p1v2[NROWS];              // pass1 second best
__device__ int   g_p1i1[NROWS];              // pass1 best index
__device__ ull   g_fbkey[NROWS];             // fallback exact key
__device__ int   g_fbcount[4];
__device__ int   g_fbrows[NROWS];
__device__ __nv_bfloat16 g_Ebh[4][KCODES * CDIM];   // E hi plane [code][c]
__device__ __nv_bfloat16 g_Ebl[4][KCODES * CDIM];   // E lo plane

// ---- helpers ----
__device__ __forceinline__ void fma2(ull& d, ull a, ull b)
{ asm("fma.rn.f32x2 %0, %1, %2, %0;" : "+l"(d) : "l"(a), "l"(b)); }
__device__ __forceinline__ ull dup2(float x)
{ ull r; asm("mov.b64 %0, {%1, %1};" : "=l"(r) : "f"(x)); return r; }
__device__ __forceinline__ float2 unpk2(ull v)
{ float2 r; asm("mov.b64 {%0, %1}, %2;" : "=f"(r.x), "=f"(r.y) : "l"(v)); return r; }
__device__ __forceinline__ void cp_async16(uint32_t dst, const void* src)
{ asm volatile("cp.async.cg.shared.global [%0], [%1], 16;" :: "r"(dst), "l"(src) : "memory"); }
__device__ __forceinline__ void mma16816(float* d, const uint32_t* a,
                                         uint32_t b0, uint32_t b1)
{
    asm volatile(
        "mma.sync.aligned.m16n8k16.row.col.f32.bf16.bf16.f32 "
        "{%0,%1,%2,%3}, {%4,%5,%6,%7}, {%8,%9}, {%0,%1,%2,%3};"
        : "+f"(d[0]), "+f"(d[1]), "+f"(d[2]), "+f"(d[3])
        : "r"(a[0]), "r"(a[1]), "r"(a[2]), "r"(a[3]), "r"(b0), "r"(b1));
}
// monotone float->unsigned map so atomicMin(ull) orders by d then index
__device__ __forceinline__ ull dkey(float d, int code)
{
    uint32_t u = __float_as_uint(d);
    u = (u >> 31) ? ~u : (u | 0x80000000u);
    return ((ull)u << 32) | (unsigned)code;
}

// ============================================================================
// exact fp32 SGEMM + bias via packed f32x2 (bit-matches reference)
// ============================================================================
__global__ __launch_bounds__(256) void sgemm_bias_kernel(
    const float* __restrict__ A, const float* __restrict__ B,
    const float* __restrict__ bias, float* __restrict__ C,
    int M, int Kd, int Nn)
{
    __shared__ __align__(16) float As[32][132];
    __shared__ __align__(16) float Bs[32][132];
    const int tid = threadIdx.x, tx = tid & 15, ty = tid >> 4;
    const int m0 = blockIdx.y * 128, n0 = blockIdx.x * 128;

    ull acc[8][4];
#pragma unroll
    for (int i = 0; i < 8; i++)
#pragma unroll
        for (int j = 0; j < 4; j++) acc[i][j] = 0ull;

    for (int k0 = 0; k0 < Kd; k0 += 32) {
#pragma unroll
        for (int i = 0; i < 16; i++) {
            int idx = tid + i * 256, mm = idx >> 5, kk = idx & 31;
            As[kk][mm] = A[(size_t)(m0 + mm) * Kd + (k0 + kk)];
        }
#pragma unroll
        for (int i = 0; i < 16; i++) {
            int idx = tid + i * 256, kk = idx >> 7, nn = idx & 127;
            Bs[kk][nn] = B[(size_t)(k0 + kk) * Nn + (n0 + nn)];
        }
        __syncthreads();
#pragma unroll
        for (int kk = 0; kk < 32; kk++) {
            float4 a0 = *(const float4*)&As[kk][ty * 4];
            float4 a1 = *(const float4*)&As[kk][64 + ty * 4];
            ull aa[8] = {dup2(a0.x), dup2(a0.y), dup2(a0.z), dup2(a0.w),
                         dup2(a1.x), dup2(a1.y), dup2(a1.z), dup2(a1.w)};
            ulonglong2 b0 = *(const ulonglong2*)&Bs[kk][tx * 4];
            ulonglong2 b1 = *(const ulonglong2*)&Bs[kk][64 + tx * 4];
            ull bb[4] = {b0.x, b0.y, b1.x, b1.y};
#pragma unroll
            for (int i = 0; i < 8; i++)
#pragma unroll
                for (int j = 0; j < 4; j++) fma2(acc[i][j], aa[i], bb[j]);
        }
        __syncthreads();
    }
#pragma unroll
    for (int i = 0; i < 8; i++) {
        int row = m0 + ((i < 4) ? (ty * 4 + i) : (64 + ty * 4 + (i - 4)));
#pragma unroll
        for (int jh = 0; jh < 2; jh++) {
            int col = n0 + (jh ? (64 + tx * 4) : (tx * 4));
            float2 p0 = unpk2(acc[i][jh * 2 + 0]);
            float2 p1 = unpk2(acc[i][jh * 2 + 1]);
            float4 v;
            v.x = __fadd_rn(p0.x, bias[col + 0]);
            v.y = __fadd_rn(p0.y, bias[col + 1]);
            v.z = __fadd_rn(p1.x, bias[col + 2]);
            v.w = __fadd_rn(p1.y, bias[col + 3]);
            *(float4*)&C[(size_t)row * Nn + col] = v;
        }
    }
}

// ============================================================================
// bf16 hi/lo split pack of all 4 codebooks + zero fallback counters
// ============================================================================
__global__ void pack_kernel(const float* __restrict__ E0,
                            const float* __restrict__ E1,
                            const float* __restrict__ E2,
                            const float* __restrict__ E3)
{
    int gid = blockIdx.x * 256 + threadIdx.x;
    if (gid < 4) g_fbcount[gid] = 0;
    int stage = gid / (KCODES * CDIM);
    int i = gid - stage * (KCODES * CDIM);
    const float* E = (stage == 0) ? E0 : (stage == 1) ? E1 : (stage == 2) ? E2 : E3;
    float f = E[i];
    __nv_bfloat16 h = __float2bfloat16(f);
    g_Ebh[stage][i] = h;
    g_Ebl[stage][i] = __float2bfloat16(f - __bfloat162float(h));
}

// ============================================================================
// ||E_k||^2 (exact sequential XLA chain), coalesced via smem staging
// ============================================================================
__global__ __launch_bounds__(256) void esq4_kernel(
    const float* __restrict__ E0, const float* __restrict__ E1,
    const float* __restrict__ E2, const float* __restrict__ E3)
{
    __shared__ float s[32][257];
    int stage = blockIdx.y;
    const float* E = (stage == 0) ? E0 : (stage == 1) ? E1 : (stage == 2) ? E2 : E3;
    int row0 = blockIdx.x * 32, tid = threadIdx.x;
#pragma unroll
    for (int i = 0; i < 32; i++) {
        int idx = tid + i * 256, r = idx >> 8, c = idx & 255;
        s[r][c] = E[(size_t)(row0 + r) * CDIM + c];
    }
    __syncthreads();
    if (tid < 32) {
        float acc = 0.f;
#pragma unroll 8
        for (int c = 0; c < CDIM; c++) {
            float v = s[tid][c];
            acc = __fadd_rn(acc, __fmul_rn(v, v));
        }
        g_esq[stage][row0 + tid] = acc;
    }
}

// ============================================================================
// ||ze||^2 (stage 0 only; later stages fused into gather)
// ============================================================================
__global__ __launch_bounds__(256) void rownorm_kernel(const float* __restrict__ ze)
{
    __shared__ float s[32][257];
    int row0 = blockIdx.x * 32, tid = threadIdx.x;
#pragma unroll
    for (int i = 0; i < 32; i++) {
        int idx = tid + i * 256, r = idx >> 8, c = idx & 255;
        s[r][c] = ze[(size_t)(row0 + r) * CDIM + c];
    }
    __syncthreads();
    if (tid < 32) {
        float acc = 0.f;
#pragma unroll 8
        for (int c = 0; c < CDIM; c++) {
            float v = s[tid][c];
            acc = __fadd_rn(acc, __fmul_rn(v, v));
        }
        g_ze2[row0 + tid] = acc;
    }
}

// ============================================================================
// PASS 1: bf16 hi/lo HMMA screening. 256 thr (8 warps), 128 rows/CTA,
// warp w owns rows w*16..w*16+15; scans all 4096 codes in 128 chunks of 32.
// d~ = esq - 2*s~ (Z row-constant drops out). Tracks min1(val,idx)/min2(val);
// rows with min2-min1 <= BAND are flagged for the exact fallback.
// smem: Ah|Al 128x264 bf16 persistent; Bh|Bl 2x(32x264) cp.async dbuf.
// ============================================================================
#define P1_ASTR 264
#define P1_BBUF 16896
#define P1_SMEM 202752

__global__ __launch_bounds__(256, 1) void vq_pass1_kernel(
    const float* __restrict__ ze, int stage)
{
    extern __shared__ char smc[];
    __nv_bfloat16* Ah = (__nv_bfloat16*)(smc);
    __nv_bfloat16* Al = (__nv_bfloat16*)(smc + 67584);
    const int tid = threadIdx.x;
    const int w = tid >> 5, lane = tid & 31;
    const int g = lane >> 2, tig = lane & 3;
    const int row0 = blockIdx.x * 128;
    const float* __restrict__ esq = g_esq[stage];
    const __nv_bfloat16* __restrict__ Ebh = g_Ebh[stage];
    const __nv_bfloat16* __restrict__ Ebl = g_Ebl[stage];
    const uint32_t sb = (uint32_t)__cvta_generic_to_shared(smc);

    // prefetch chunk 0 (codes 0..31), hi+lo planes
#pragma unroll
    for (int i = 0; i < 4; i++) {
        int idx = tid + i * 256;            // 0..1023
        int cl = idx >> 5, seg = idx & 31;
        uint32_t off = (uint32_t)(cl * 528 + seg * 16);
        cp_async16(sb + 135168u + off, Ebh + (size_t)cl * CDIM + seg * 8);
        cp_async16(sb + 168960u + off, Ebl + (size_t)cl * CDIM + seg * 8);
    }
    asm volatile("cp.async.commit_group;" ::: "memory");

    // fill persistent A planes (split ze into bf16 hi+lo)
#pragma unroll 4
    for (int i = 0; i < 32; i++) {
        int idx = tid + i * 256;            // 0..8191 float4 units
        int r = idx >> 6, c4 = idx & 63;
        float4 f = *(const float4*)(ze + (size_t)(row0 + r) * CDIM + c4 * 4);
        __nv_bfloat162 h01, h23, l01, l23;
        h01.x = __float2bfloat16(f.x); l01.x = __float2bfloat16(f.x - __bfloat162float(h01.x));
        h01.y = __float2bfloat16(f.y); l01.y = __float2bfloat16(f.y - __bfloat162float(h01.y));
        h23.x = __float2bfloat16(f.z); l23.x = __float2bfloat16(f.z - __bfloat162float(h23.x));
        h23.y = __float2bfloat16(f.w); l23.y = __float2bfloat16(f.w - __bfloat162float(h23.y));
        int o = r * P1_ASTR + c4 * 4;
        *(__nv_bfloat162*)(Ah + o) = h01; *(__nv_bfloat162*)(Ah + o + 2) = h23;
        *(__nv_bfloat162*)(Al + o) = l01; *(__nv_bfloat162*)(Al + o + 2) = l23;
    }

    float m1[2] = {3.4e38f, 3.4e38f}, m2[2] = {3.4e38f, 3.4e38f};
    int   i1[2] = {0, 0};
    const int arow = (w * 16 + g) * P1_ASTR;

    for (int t = 0; t < 128; t++) {
        asm volatile("cp.async.wait_group 0;" ::: "memory");
        __syncthreads();

        if (t < 127) {
            const int code1 = (t + 1) * 32;
            const uint32_t bo = (uint32_t)(((t + 1) & 1) * P1_BBUF);
#pragma unroll
            for (int i = 0; i < 4; i++) {
                int idx = tid + i * 256;
                int cl = idx >> 5, seg = idx & 31;
                uint32_t off = bo + (uint32_t)(cl * 528 + seg * 16);
                cp_async16(sb + 135168u + off, Ebh + (size_t)(code1 + cl) * CDIM + seg * 8);
                cp_async16(sb + 168960u + off, Ebl + (size_t)(code1 + cl) * CDIM + seg * 8);
            }
            asm volatile("cp.async.commit_group;" ::: "memory");
        }

        const __nv_bfloat16* Bph = (__nv_bfloat16*)(smc + 135168 + (t & 1) * P1_BBUF);
        const __nv_bfloat16* Bpl = (__nv_bfloat16*)(smc + 168960 + (t & 1) * P1_BBUF);

        float acc[4][4];
#pragma unroll
        for (int nt = 0; nt < 4; nt++)
#pragma unroll
            for (int j = 0; j < 4; j++) acc[nt][j] = 0.f;

#pragma unroll 4
        for (int k = 0; k < 16; k++) {
            const int kk = k * 16;
            uint32_t ah[4], al[4];
            int ao = arow + kk + 2 * tig;
            ah[0] = *(const uint32_t*)(Ah + ao);
            ah[1] = *(const uint32_t*)(Ah + ao + 8 * P1_ASTR);
            ah[2] = *(const uint32_t*)(Ah + ao + 8);
            ah[3] = *(const uint32_t*)(Ah + ao + 8 * P1_ASTR + 8);
            al[0] = *(const uint32_t*)(Al + ao);
            al[1] = *(const uint32_t*)(Al + ao + 8 * P1_ASTR);
            al[2] = *(const uint32_t*)(Al + ao + 8);
            al[3] = *(const uint32_t*)(Al + ao + 8 * P1_ASTR + 8);
            uint32_t bh[4][2], bl[4][2];
#pragma unroll
            for (int nt = 0; nt < 4; nt++) {
                int bo = (nt * 8 + g) * P1_ASTR + kk + 2 * tig;
                bh[nt][0] = *(const uint32_t*)(Bph + bo);
                bh[nt][1] = *(const uint32_t*)(Bph + bo + 8);
                bl[nt][0] = *(const uint32_t*)(Bpl + bo);
                bl[nt][1] = *(const uint32_t*)(Bpl + bo + 8);
            }
#pragma unroll
            for (int nt = 0; nt < 4; nt++) mma16816(acc[nt], ah, bh[nt][0], bh[nt][1]);
#pragma unroll
            for (int nt = 0; nt < 4; nt++) mma16816(acc[nt], ah, bl[nt][0], bl[nt][1]);
#pragma unroll
            for (int nt = 0; nt < 4; nt++) mma16816(acc[nt], al, bh[nt][0], bh[nt][1]);
        }

        // epilogue: per-thread min1/min2 over this chunk's codes
        const int code0 = t * 32;
#pragma unroll
        for (int nt = 0; nt < 4; nt++) {
            int c0 = code0 + nt * 8 + 2 * tig;
            float e0 = esq[c0], e1 = esq[c0 + 1];
#pragma unroll
            for (int s = 0; s < 2; s++) {       // s=0: row g, s=1: row g+8
                float d0 = fmaf(-2.f, acc[nt][s * 2 + 0], e0);
                if (d0 < m1[s]) { m2[s] = m1[s]; m1[s] = d0; i1[s] = c0; }
                else if (d0 < m2[s]) m2[s] = d0;
                float d1 = fmaf(-2.f, acc[nt][s * 2 + 1], e1);
                if (d1 < m1[s]) { m2[s] = m1[s]; m1[s] = d1; i1[s] = c0 + 1; }
                else if (d1 < m2[s]) m2[s] = d1;
            }
        }
    }

    // merge across the 4 tig lanes sharing each row
#pragma unroll
    for (int s = 0; s < 2; s++) {
#pragma unroll
        for (int off = 1; off <= 2; off <<= 1) {
            float o1 = __shfl_xor_sync(0xffffffffu, m1[s], off);
            int   oi = __shfl_xor_sync(0xffffffffu, i1[s], off);
            float o2 = __shfl_xor_sync(0xffffffffu, m2[s], off);
            float nm2 = fminf(fmaxf(m1[s], o1), fminf(m2[s], o2));
            if (o1 < m1[s] || (o1 == m1[s] && oi < i1[s])) { m1[s] = o1; i1[s] = oi; }
            m2[s] = nm2;
        }
    }
    if (tig == 0) {
#pragma unroll
        for (int s = 0; s < 2; s++) {
            int row = row0 + w * 16 + g + s * 8;
            g_p1v1[row] = m1[s];
            g_p1v2[row] = m2[s];
            g_p1i1[row] = i1[s];
            g_fbkey[row] = ~0ull;
            if (m2[s] - m1[s] <= BAND) {
                int pos = atomicAdd(&g_fbcount[stage], 1);
                g_fbrows[pos] = row;
            }
        }
    }
}

// ============================================================================
// PASS 2: exact fallback. grid (32 row-batches, 8 code-segments), 256 thr.
// Each block: 64 gathered rows x 512 codes, exact reference arithmetic
// (single ascending-c fma chain; d = fl(fl(Z - fl(2s)) + e)); per-row min
// merged via atomicMin on monotone key -> exact argmin, lowest-index ties.
// dyn smem: As 256x68 (gathered ze, c-major) | Bs 32x132 | rows 64 = 86,784 B
// ============================================================================
#define FB_SMEM ((256 * 68 + 32 * 132) * 4 + 256)

__global__ __launch_bounds__(256) void vq_fallback_kernel(
    const float* __restrict__ ze, const float* __restrict__ E, int stage)
{
    extern __shared__ __align__(16) float fsm[];
    float* As = fsm;                       // [256 c][68]
    float* Bs = fsm + 256 * 68;            // [32 kk][132]
    int* rowsm = (int*)(fsm + 256 * 68 + 32 * 132);

    const int cnt = g_fbcount[stage];
    const int tid = threadIdx.x, tx = tid & 15, ty = tid >> 4;
    const int seg0 = blockIdx.y * 512;
    const float* __restrict__ esq = g_esq[stage];

    for (int base = blockIdx.x * 64; base < cnt; base += gridDim.x * 64) {
        __syncthreads();
        if (tid < 64) rowsm[tid] = (base + tid < cnt) ? g_fbrows[base + tid] : -1;
        __syncthreads();
#pragma unroll 4
        for (int i = 0; i < 64; i++) {
            int idx = tid + i * 256;
            int r = idx >> 8, c = idx & 255;
            int rr = rowsm[r];
            As[c * 68 + r] = (rr >= 0) ? ze[(size_t)rr * CDIM + c] : 0.f;
        }
        float zrow[4]; int rid[4];
#pragma unroll
        for (int i = 0; i < 4; i++) {
            rid[i] = rowsm[ty * 4 + i];
            zrow[i] = (rid[i] >= 0) ? g_ze2[rid[i]] : 0.f;
        }
        float bestv[4]; int besti[4];
#pragma unroll
        for (int i = 0; i < 4; i++) { bestv[i] = 3.4e38f; besti[i] = 0; }
        __syncthreads();

        for (int cb = 0; cb < 512; cb += 128) {
            ull acc[4][4];
#pragma unroll
            for (int i = 0; i < 4; i++)
#pragma unroll
                for (int j = 0; j < 4; j++) acc[i][j] = 0ull;

            for (int c0 = 0; c0 < CDIM; c0 += 32) {
#pragma unroll
                for (int i = 0; i < 16; i++) {
                    int idx = tid + i * 256;
                    int code = idx >> 5, kk = idx & 31;
                    Bs[kk * 132 + code] =
                        E[(size_t)(seg0 + cb + code) * CDIM + c0 + kk];
                }
                __syncthreads();
#pragma unroll
                for (int kk = 0; kk < 32; kk++) {
                    const float* ar = As + (c0 + kk) * 68;
                    const float* br = Bs + kk * 132;
                    float4 a0 = *(const float4*)&ar[ty * 4];
                    ull aa[4] = {dup2(a0.x), dup2(a0.y), dup2(a0.z), dup2(a0.w)};
                    ulonglong2 b0 = *(const ulonglong2*)&br[tx * 4];
                    ulonglong2 b1 = *(const ulonglong2*)&br[64 + tx * 4];
                    ull bb[4] = {b0.x, b0.y, b1.x, b1.y};
#pragma unroll
                    for (int i = 0; i < 4; i++)
#pragma unroll
                        for (int j = 0; j < 4; j++) fma2(acc[i][j], aa[i], bb[j]);
                }
                __syncthreads();
            }
            // exact d + local argmin
#pragma unroll
            for (int jh = 0; jh < 2; jh++) {
#pragma unroll
                for (int h = 0; h < 2; h++) {
                    int j2 = jh * 2 + h;
                    int col = seg0 + cb + jh * 64 + tx * 4 + h * 2;
                    float eq0 = esq[col], eq1 = esq[col + 1];
#pragma unroll
                    for (int i = 0; i < 4; i++) {
                        float2 pv = unpk2(acc[i][j2]);
                        float v0 = __fadd_rn(__fadd_rn(zrow[i], -__fmul_rn(2.f, pv.x)), eq0);
                        if (v0 < bestv[i]) { bestv[i] = v0; besti[i] = col; }
                        float v1 = __fadd_rn(__fadd_rn(zrow[i], -__fmul_rn(2.f, pv.y)), eq1);
                        if (v1 < bestv[i]) { bestv[i] = v1; besti[i] = col + 1; }
                    }
                }
            }
        }

        // butterfly over the 16 tx lanes sharing each row (within half-warp)
#pragma unroll
        for (int i = 0; i < 4; i++) {
            float v = bestv[i]; int ix = besti[i];
#pragma unroll
            for (int off = 1; off <= 8; off <<= 1) {
                float ov = __shfl_xor_sync(0xffffffffu, v, off);
                int   oi = __shfl_xor_sync(0xffffffffu, ix, off);
                if (ov < v || (ov == v && oi < ix)) { v = ov; ix = oi; }
            }
            if (tx == 0 && rid[i] >= 0)
                atomicMin(&g_fbkey[rid[i]], dkey(v, ix));
        }
    }
}

// ============================================================================
// Gather: resolve nn (fallback key if flagged else pass1); zq = E[nn];
// residual; zq_sum; stage-3 straight-through; next-stage ||ze||^2 fused.
// ============================================================================
__global__ void gather_kernel(const float* __restrict__ ze,
                              const float* __restrict__ E,
                              float* __restrict__ zq_out,
                              float* __restrict__ ze_next,
                              float* __restrict__ nn_f,
                              const float* __restrict__ ze1,
                              int stage)
{
    __shared__ float buf[CDIM];
    int row = blockIdx.x, c = threadIdx.x;
    int idx = (g_p1v2[row] - g_p1v1[row] <= BAND)
                  ? (int)(unsigned)(g_fbkey[row] & 0xffffffffull)
                  : g_p1i1[row];

    float q = E[(size_t)idx * CDIM + c];
    size_t o = (size_t)row * CDIM + c;
    zq_out[o] = q;
    if (ze_next) {
        float zn = __fadd_rn(ze[o], -q);
        ze_next[o] = zn;
        buf[c] = zn;
    }
    float s = (stage == 0) ? q : __fadd_rn(g_zqsum[o], q);
    if (stage == 3) {
        float z1 = ze1[o];
        s = __fadd_rn(z1, __fadd_rn(s, -z1));
    }
    g_zqsum[o] = s;
    if (c == 0) nn_f[row] = (float)idx;

    if (ze_next) {
        __syncthreads();
        if (c == 0) {
            float acc = 0.f;
#pragma unroll 8
            for (int i = 0; i < CDIM; i++)
                acc = __fadd_rn(acc, __fmul_rn(buf[i], buf[i]));
            g_ze2[row] = acc;
        }
    }
}

// ============================================================================
// kernel_launch — output: x_hat | ze_1..4 | zq_1..4 | nn_1..4
// ============================================================================
extern "C" void kernel_launch(void* const* d_in, const int* in_sizes, int n_in,
                              void* d_out, int out_size)
{
    const float* x     = (const float*)d_in[0];
    const float* W_enc = (const float*)d_in[1];
    const float* b_enc = (const float*)d_in[2];
    const float* E[4]  = {(const float*)d_in[3], (const float*)d_in[4],
                          (const float*)d_in[5], (const float*)d_in[6]};
    const float* W_dec = (const float*)d_in[7];
    const float* b_dec = (const float*)d_in[8];

    float* out = (float*)d_out;
    const size_t NC     = (size_t)NROWS * CDIM;
    const size_t OFF_ZE = (size_t)NROWS * INDIM;
    const size_t OFF_ZQ = OFF_ZE + 4 * NC;
    const size_t OFF_NN = OFF_ZQ + 4 * NC;
    const float* ze1 = out + OFF_ZE;

    void* zqsum_ptr = nullptr;
    cudaGetSymbolAddress(&zqsum_ptr, g_zqsum);

    cudaFuncSetAttribute(vq_pass1_kernel,
                         cudaFuncAttributeMaxDynamicSharedMemorySize, P1_SMEM);
    cudaFuncSetAttribute(vq_fallback_kernel,
                         cudaFuncAttributeMaxDynamicSharedMemorySize, FB_SMEM);

    // one-time preprocessing
    esq4_kernel<<<dim3(KCODES / 32, 4), 256>>>(E[0], E[1], E[2], E[3]);
    pack_kernel<<<(4 * KCODES * CDIM) / 256, 256>>>(E[0], E[1], E[2], E[3]);

    // encoder
    sgemm_bias_kernel<<<dim3(CDIM / 128, NROWS / 128), 256>>>(
        x, W_enc, b_enc, out + OFF_ZE, NROWS, INDIM, CDIM);
    rownorm_kernel<<<NROWS / 32, 256>>>(out + OFF_ZE);

    // 4 sequential VQ stages
    for (int s = 0; s < 4; s++) {
        const float* zes = out + OFF_ZE + (size_t)s * NC;
        vq_pass1_kernel<<<NROWS / 128, 256, P1_SMEM>>>(zes, s);
        vq_fallback_kernel<<<dim3(32, 8), 256, FB_SMEM>>>(zes, E[s], s);
        float* zenext = (s < 3) ? (out + OFF_ZE + (size_t)(s + 1) * NC) : nullptr;
        gather_kernel<<<NROWS, 256>>>(zes, E[s],
                                      out + OFF_ZQ + (size_t)s * NC,
                                      zenext,
                                      out + OFF_NN + (size_t)s * NROWS,
                                      ze1, s);
    }

    // decoder
    sgemm_bias_kernel<<<dim3(INDIM / 128, NROWS / 128), 256>>>(
        (const float*)zqsum_ptr, W_dec, b_dec, out, NROWS, CDIM, INDIM);
}

// round 12
// speedup vs baseline: 1.9573x; 1.0617x over previous
#include <cuda_runtime.h>
#include <cuda_bf16.h>
#include <cstddef>
#include <cstdint>

#define NROWS 16384
#define INDIM 768
#define CDIM  256
#define KCODES 4096
#define BAND  8e-3f

typedef unsigned long long ull;

// ---- device scratch ----
__device__ float g_zqsum[NROWS * CDIM];
__device__ float g_esq[4][KCODES];
__device__ float g_ze2[NROWS];
__device__ float g_p1v1[NROWS];
__device__ float g_p1v2[NROWS];
__device__ int   g_p1i1[NROWS];
__device__ ull   g_fbkey[NROWS];
__device__ int   g_fbcount[4];
__device__ int   g_fbrows[NROWS];
// codebook bf16 planes, TILE-SWIZZLED layout:
//   tile = code>>5 (128 tiles of 32 codes), row = code&31, word = c>>1
//   elem offset = tile*8192 + row*256 + ((word ^ ((row&7)<<2)) << 1) + (c&1)
// -> each tile is 16KB contiguous (bulk-copyable), reads conflict-free.
__device__ __nv_bfloat16 g_PBh[4][KCODES * CDIM];
__device__ __nv_bfloat16 g_PBl[4][KCODES * CDIM];

// ---- helpers ----
__device__ __forceinline__ void fma2(ull& d, ull a, ull b)
{ asm("fma.rn.f32x2 %0, %1, %2, %0;" : "+l"(d) : "l"(a), "l"(b)); }
__device__ __forceinline__ ull dup2(float x)
{ ull r; asm("mov.b64 %0, {%1, %1};" : "=l"(r) : "f"(x)); return r; }
__device__ __forceinline__ float2 unpk2(ull v)
{ float2 r; asm("mov.b64 {%0, %1}, %2;" : "=f"(r.x), "=f"(r.y) : "l"(v)); return r; }
__device__ __forceinline__ void mma16816(float* d, const uint32_t* a,
                                         uint32_t b0, uint32_t b1)
{
    asm volatile(
        "mma.sync.aligned.m16n8k16.row.col.f32.bf16.bf16.f32 "
        "{%0,%1,%2,%3}, {%4,%5,%6,%7}, {%8,%9}, {%0,%1,%2,%3};"
        : "+f"(d[0]), "+f"(d[1]), "+f"(d[2]), "+f"(d[3])
        : "r"(a[0]), "r"(a[1]), "r"(a[2]), "r"(a[3]), "r"(b0), "r"(b1));
}
__device__ __forceinline__ ull dkey(float d, int code)
{
    uint32_t u = __float_as_uint(d);
    u = (u >> 31) ? ~u : (u | 0x80000000u);
    return ((ull)u << 32) | (unsigned)code;
}
// mbarrier primitives
__device__ __forceinline__ void mbar_init(uint32_t a)
{ asm volatile("mbarrier.init.shared.b64 [%0], 1;" :: "r"(a) : "memory"); }
__device__ __forceinline__ void mbar_expect(uint32_t a, uint32_t bytes)
{ asm volatile("mbarrier.arrive.expect_tx.shared.b64 _, [%0], %1;" :: "r"(a), "r"(bytes) : "memory"); }
__device__ __forceinline__ void mbar_wait(uint32_t a, int phase)
{
    asm volatile(
        "{\n\t.reg .pred p;\n"
        "L%=:\n\t"
        "mbarrier.try_wait.parity.acquire.cta.shared::cta.b64 p, [%0], %1;\n\t"
        "@!p bra L%=;\n\t}"
        :: "r"(a), "r"(phase) : "memory");
}
__device__ __forceinline__ void bulk_cp(uint32_t dst, const void* src,
                                        uint32_t bytes, uint32_t mbar)
{
    asm volatile(
        "cp.async.bulk.shared::cta.global.mbarrier::complete_tx::bytes "
        "[%0], [%1], %2, [%3];"
        :: "r"(dst), "l"(src), "r"(bytes), "r"(mbar) : "memory");
}

// ============================================================================
// exact fp32 SGEMM + bias via packed f32x2 (bit-matches reference)
// ============================================================================
__global__ __launch_bounds__(256) void sgemm_bias_kernel(
    const float* __restrict__ A, const float* __restrict__ B,
    const float* __restrict__ bias, float* __restrict__ C,
    int M, int Kd, int Nn)
{
    __shared__ __align__(16) float As[32][132];
    __shared__ __align__(16) float Bs[32][132];
    const int tid = threadIdx.x, tx = tid & 15, ty = tid >> 4;
    const int m0 = blockIdx.y * 128, n0 = blockIdx.x * 128;

    ull acc[8][4];
#pragma unroll
    for (int i = 0; i < 8; i++)
#pragma unroll
        for (int j = 0; j < 4; j++) acc[i][j] = 0ull;

    for (int k0 = 0; k0 < Kd; k0 += 32) {
#pragma unroll
        for (int i = 0; i < 16; i++) {
            int idx = tid + i * 256, mm = idx >> 5, kk = idx & 31;
            As[kk][mm] = A[(size_t)(m0 + mm) * Kd + (k0 + kk)];
        }
#pragma unroll
        for (int i = 0; i < 16; i++) {
            int idx = tid + i * 256, kk = idx >> 7, nn = idx & 127;
            Bs[kk][nn] = B[(size_t)(k0 + kk) * Nn + (n0 + nn)];
        }
        __syncthreads();
#pragma unroll
        for (int kk = 0; kk < 32; kk++) {
            float4 a0 = *(const float4*)&As[kk][ty * 4];
            float4 a1 = *(const float4*)&As[kk][64 + ty * 4];
            ull aa[8] = {dup2(a0.x), dup2(a0.y), dup2(a0.z), dup2(a0.w),
                         dup2(a1.x), dup2(a1.y), dup2(a1.z), dup2(a1.w)};
            ulonglong2 b0 = *(const ulonglong2*)&Bs[kk][tx * 4];
            ulonglong2 b1 = *(const ulonglong2*)&Bs[kk][64 + tx * 4];
            ull bb[4] = {b0.x, b0.y, b1.x, b1.y};
#pragma unroll
            for (int i = 0; i < 8; i++)
#pragma unroll
                for (int j = 0; j < 4; j++) fma2(acc[i][j], aa[i], bb[j]);
        }
        __syncthreads();
    }
#pragma unroll
    for (int i = 0; i < 8; i++) {
        int row = m0 + ((i < 4) ? (ty * 4 + i) : (64 + ty * 4 + (i - 4)));
#pragma unroll
        for (int jh = 0; jh < 2; jh++) {
            int col = n0 + (jh ? (64 + tx * 4) : (tx * 4));
            float2 p0 = unpk2(acc[i][jh * 2 + 0]);
            float2 p1 = unpk2(acc[i][jh * 2 + 1]);
            float4 v;
            v.x = __fadd_rn(p0.x, bias[col + 0]);
            v.y = __fadd_rn(p0.y, bias[col + 1]);
            v.z = __fadd_rn(p1.x, bias[col + 2]);
            v.w = __fadd_rn(p1.y, bias[col + 3]);
            *(float4*)&C[(size_t)row * Nn + col] = v;
        }
    }
}

// ============================================================================
// pack codebooks into tile-swizzled bf16 hi/lo planes + zero fb counters.
// thread per (stage, code, word): word = c/2.
// ============================================================================
__global__ void pack_kernel(const float* __restrict__ E0,
                            const float* __restrict__ E1,
                            const float* __restrict__ E2,
                            const float* __restrict__ E3)
{
    int gid = blockIdx.x * 256 + threadIdx.x;   // 0 .. 4*4096*128-1
    if (gid < 4) g_fbcount[gid] = 0;
    int stage = gid >> 19;                      // 4096*128 = 2^19
    int rem = gid & 524287;
    int code = rem >> 7, word = rem & 127;
    const float* E = (stage == 0) ? E0 : (stage == 1) ? E1 : (stage == 2) ? E2 : E3;
    float f0 = E[(size_t)code * CDIM + word * 2];
    float f1 = E[(size_t)code * CDIM + word * 2 + 1];
    __nv_bfloat16 h0 = __float2bfloat16(f0);
    __nv_bfloat16 h1 = __float2bfloat16(f1);
    __nv_bfloat16 l0 = __float2bfloat16(f0 - __bfloat162float(h0));
    __nv_bfloat16 l1 = __float2bfloat16(f1 - __bfloat162float(h1));
    int tile = code >> 5, row = code & 31;
    int off = tile * 8192 + row * 256 + ((word ^ ((row & 7) << 2)) << 1);
    g_PBh[stage][off] = h0; g_PBh[stage][off + 1] = h1;
    g_PBl[stage][off] = l0; g_PBl[stage][off + 1] = l1;
}

// ============================================================================
// ||E_k||^2 (exact sequential XLA chain), coalesced via smem staging
// ============================================================================
__global__ __launch_bounds__(256) void esq4_kernel(
    const float* __restrict__ E0, const float* __restrict__ E1,
    const float* __restrict__ E2, const float* __restrict__ E3)
{
    __shared__ float s[32][257];
    int stage = blockIdx.y;
    const float* E = (stage == 0) ? E0 : (stage == 1) ? E1 : (stage == 2) ? E2 : E3;
    int row0 = blockIdx.x * 32, tid = threadIdx.x;
#pragma unroll
    for (int i = 0; i < 32; i++) {
        int idx = tid + i * 256, r = idx >> 8, c = idx & 255;
        s[r][c] = E[(size_t)(row0 + r) * CDIM + c];
    }
    __syncthreads();
    if (tid < 32) {
        float acc = 0.f;
#pragma unroll 8
        for (int c = 0; c < CDIM; c++) {
            float v = s[tid][c];
            acc = __fadd_rn(acc, __fmul_rn(v, v));
        }
        g_esq[stage][row0 + tid] = acc;
    }
}

// ============================================================================
// ||ze||^2 (stage 0 only; later stages fused into gather)
// ============================================================================
__global__ __launch_bounds__(256) void rownorm_kernel(const float* __restrict__ ze)
{
    __shared__ float s[32][257];
    int row0 = blockIdx.x * 32, tid = threadIdx.x;
#pragma unroll
    for (int i = 0; i < 32; i++) {
        int idx = tid + i * 256, r = idx >> 8, c = idx & 255;
        s[r][c] = ze[(size_t)(row0 + r) * CDIM + c];
    }
    __syncthreads();
    if (tid < 32) {
        float acc = 0.f;
#pragma unroll 8
        for (int c = 0; c < CDIM; c++) {
            float v = s[tid][c];
            acc = __fadd_rn(acc, __fmul_rn(v, v));
        }
        g_ze2[row0 + tid] = acc;
    }
}

// ============================================================================
// PASS 1: bf16 hi/lo HMMA screening, bulk-copied B tiles.
// 256 thr (8 warps), 128 rows/CTA; warp w rows w*16..+15; 128 chunks of 32
// codes streamed via cp.async.bulk (2 x 16KB per chunk, mbarrier expect_tx,
// double buffered). B smem layout = swizzled tiles (see g_PBh) -> reads are
// bank-conflict-free. d~ = esq - 2*s~; min1/min2 band-flagging as before.
// smem: Ah|Al 128x264 bf16 persistent (135168 B); B 2 x 32KB = 65536 B.
// ============================================================================
#define P1_ASTR 264
#define P1_BOFF 135168
#define P1_SMEM (135168 + 65536)

__global__ __launch_bounds__(256, 1) void vq_pass1_kernel(
    const float* __restrict__ ze, int stage)
{
    extern __shared__ char smc[];
    __nv_bfloat16* Ah = (__nv_bfloat16*)(smc);
    __nv_bfloat16* Al = (__nv_bfloat16*)(smc + 67584);
    __shared__ __align__(8) ull mbar[2];

    const int tid = threadIdx.x;
    const int w = tid >> 5, lane = tid & 31;
    const int g = lane >> 2, tig = lane & 3;
    const int row0 = blockIdx.x * 128;
    const float* __restrict__ esq = g_esq[stage];
    const __nv_bfloat16* __restrict__ PBh = g_PBh[stage];
    const __nv_bfloat16* __restrict__ PBl = g_PBl[stage];
    const uint32_t sb = (uint32_t)__cvta_generic_to_shared(smc);
    const uint32_t mb0 = (uint32_t)__cvta_generic_to_shared(&mbar[0]);
    const uint32_t mb1 = (uint32_t)__cvta_generic_to_shared(&mbar[1]);

    if (tid == 0) { mbar_init(mb0); mbar_init(mb1); }
    __syncthreads();

    // prefetch chunk 0 into buffer 0 (hi 16KB + lo 16KB)
    if (tid == 0) {
        mbar_expect(mb0, 32768u);
        bulk_cp(sb + P1_BOFF, PBh, 16384u, mb0);
        bulk_cp(sb + P1_BOFF + 16384u, PBl, 16384u, mb0);
    }

    // fill persistent A planes (split ze into bf16 hi+lo)
#pragma unroll 4
    for (int i = 0; i < 32; i++) {
        int idx = tid + i * 256;            // 0..8191 float4 units
        int r = idx >> 6, c4 = idx & 63;
        float4 f = *(const float4*)(ze + (size_t)(row0 + r) * CDIM + c4 * 4);
        __nv_bfloat162 h01, h23, l01, l23;
        h01.x = __float2bfloat16(f.x); l01.x = __float2bfloat16(f.x - __bfloat162float(h01.x));
        h01.y = __float2bfloat16(f.y); l01.y = __float2bfloat16(f.y - __bfloat162float(h01.y));
        h23.x = __float2bfloat16(f.z); l23.x = __float2bfloat16(f.z - __bfloat162float(h23.x));
        h23.y = __float2bfloat16(f.w); l23.y = __float2bfloat16(f.w - __bfloat162float(h23.y));
        int o = r * P1_ASTR + c4 * 4;
        *(__nv_bfloat162*)(Ah + o) = h01; *(__nv_bfloat162*)(Ah + o + 2) = h23;
        *(__nv_bfloat162*)(Al + o) = l01; *(__nv_bfloat162*)(Al + o + 2) = l23;
    }

    float m1[2] = {3.4e38f, 3.4e38f}, m2[2] = {3.4e38f, 3.4e38f};
    int   i1[2] = {0, 0};
    const int arow = (w * 16 + g) * P1_ASTR;
    const int swz = g << 2;                 // word-swizzle term (row&7 == g)

    for (int t = 0; t < 128; t++) {
        mbar_wait((t & 1) ? mb1 : mb0, (t >> 1) & 1);
        __syncthreads();   // all warps done with the OTHER buffer's compute

        if (t < 127 && tid == 0) {
            const uint32_t dst = sb + P1_BOFF + ((t + 1) & 1) * 32768u;
            const uint32_t mb = ((t + 1) & 1) ? mb1 : mb0;
            const size_t so = (size_t)(t + 1) * 8192;
            mbar_expect(mb, 32768u);
            bulk_cp(dst, PBh + so, 16384u, mb);
            bulk_cp(dst + 16384u, PBl + so, 16384u, mb);
        }

        const char* Bph = smc + P1_BOFF + (t & 1) * 32768;
        const char* Bpl = Bph + 16384;

        float acc[4][4];
#pragma unroll
        for (int nt = 0; nt < 4; nt++)
#pragma unroll
            for (int j = 0; j < 4; j++) acc[nt][j] = 0.f;

#pragma unroll 4
        for (int k = 0; k < 16; k++) {
            const int kk = k * 16;
            uint32_t ah[4], al[4];
            int ao = arow + kk + 2 * tig;
            ah[0] = *(const uint32_t*)(Ah + ao);
            ah[1] = *(const uint32_t*)(Ah + ao + 8 * P1_ASTR);
            ah[2] = *(const uint32_t*)(Ah + ao + 8);
            ah[3] = *(const uint32_t*)(Ah + ao + 8 * P1_ASTR + 8);
            al[0] = *(const uint32_t*)(Al + ao);
            al[1] = *(const uint32_t*)(Al + ao + 8 * P1_ASTR);
            al[2] = *(const uint32_t*)(Al + ao + 8);
            al[3] = *(const uint32_t*)(Al + ao + 8 * P1_ASTR + 8);

            const int w0 = ((kk >> 1) + tig) ^ swz;        // swizzled words
            const int w1 = ((kk >> 1) + tig + 4) ^ swz;
            uint32_t bh[4][2], bl[4][2];
#pragma unroll
            for (int nt = 0; nt < 4; nt++) {
                int rb = (nt * 8 + g) * 512;
                bh[nt][0] = *(const uint32_t*)(Bph + rb + w0 * 4);
                bh[nt][1] = *(const uint32_t*)(Bph + rb + w1 * 4);
                bl[nt][0] = *(const uint32_t*)(Bpl + rb + w0 * 4);
                bl[nt][1] = *(const uint32_t*)(Bpl + rb + w1 * 4);
            }
#pragma unroll
            for (int nt = 0; nt < 4; nt++) mma16816(acc[nt], ah, bh[nt][0], bh[nt][1]);
#pragma unroll
            for (int nt = 0; nt < 4; nt++) mma16816(acc[nt], ah, bl[nt][0], bl[nt][1]);
#pragma unroll
            for (int nt = 0; nt < 4; nt++) mma16816(acc[nt], al, bh[nt][0], bh[nt][1]);
        }

        // epilogue: per-thread min1/min2 over this chunk's codes
        const int code0 = t * 32;
#pragma unroll
        for (int nt = 0; nt < 4; nt++) {
            int c0 = code0 + nt * 8 + 2 * tig;
            float e0 = esq[c0], e1 = esq[c0 + 1];
#pragma unroll
            for (int s = 0; s < 2; s++) {
                float d0 = fmaf(-2.f, acc[nt][s * 2 + 0], e0);
                if (d0 < m1[s]) { m2[s] = m1[s]; m1[s] = d0; i1[s] = c0; }
                else if (d0 < m2[s]) m2[s] = d0;
                float d1 = fmaf(-2.f, acc[nt][s * 2 + 1], e1);
                if (d1 < m1[s]) { m2[s] = m1[s]; m1[s] = d1; i1[s] = c0 + 1; }
                else if (d1 < m2[s]) m2[s] = d1;
            }
        }
    }

    // merge across the 4 tig lanes sharing each row
#pragma unroll
    for (int s = 0; s < 2; s++) {
#pragma unroll
        for (int off = 1; off <= 2; off <<= 1) {
            float o1 = __shfl_xor_sync(0xffffffffu, m1[s], off);
            int   oi = __shfl_xor_sync(0xffffffffu, i1[s], off);
            float o2 = __shfl_xor_sync(0xffffffffu, m2[s], off);
            float nm2 = fminf(fmaxf(m1[s], o1), fminf(m2[s], o2));
            if (o1 < m1[s] || (o1 == m1[s] && oi < i1[s])) { m1[s] = o1; i1[s] = oi; }
            m2[s] = nm2;
        }
    }
    if (tig == 0) {
#pragma unroll
        for (int s = 0; s < 2; s++) {
            int row = row0 + w * 16 + g + s * 8;
            g_p1v1[row] = m1[s];
            g_p1v2[row] = m2[s];
            g_p1i1[row] = i1[s];
            g_fbkey[row] = ~0ull;
            if (m2[s] - m1[s] <= BAND) {
                int pos = atomicAdd(&g_fbcount[stage], 1);
                g_fbrows[pos] = row;
            }
        }
    }
}

// ============================================================================
// PASS 2: exact fallback (unchanged; exact reference arithmetic + atomicMin
// on monotone key -> exact argmin, lowest-index ties).
// ============================================================================
#define FB_SMEM ((256 * 68 + 32 * 132) * 4 + 256)

__global__ __launch_bounds__(256) void vq_fallback_kernel(
    const float* __restrict__ ze, const float* __restrict__ E, int stage)
{
    extern __shared__ __align__(16) float fsm[];
    float* As = fsm;
    float* Bs = fsm + 256 * 68;
    int* rowsm = (int*)(fsm + 256 * 68 + 32 * 132);

    const int cnt = g_fbcount[stage];
    const int tid = threadIdx.x, tx = tid & 15, ty = tid >> 4;
    const int seg0 = blockIdx.y * 512;
    const float* __restrict__ esq = g_esq[stage];

    for (int base = blockIdx.x * 64; base < cnt; base += gridDim.x * 64) {
        __syncthreads();
        if (tid < 64) rowsm[tid] = (base + tid < cnt) ? g_fbrows[base + tid] : -1;
        __syncthreads();
#pragma unroll 4
        for (int i = 0; i < 64; i++) {
            int idx = tid + i * 256;
            int r = idx >> 8, c = idx & 255;
            int rr = rowsm[r];
            As[c * 68 + r] = (rr >= 0) ? ze[(size_t)rr * CDIM + c] : 0.f;
        }
        float zrow[4]; int rid[4];
#pragma unroll
        for (int i = 0; i < 4; i++) {
            rid[i] = rowsm[ty * 4 + i];
            zrow[i] = (rid[i] >= 0) ? g_ze2[rid[i]] : 0.f;
        }
        float bestv[4]; int besti[4];
#pragma unroll
        for (int i = 0; i < 4; i++) { bestv[i] = 3.4e38f; besti[i] = 0; }
        __syncthreads();

        for (int cb = 0; cb < 512; cb += 128) {
            ull acc[4][4];
#pragma unroll
            for (int i = 0; i < 4; i++)
#pragma unroll
                for (int j = 0; j < 4; j++) acc[i][j] = 0ull;

            for (int c0 = 0; c0 < CDIM; c0 += 32) {
#pragma unroll
                for (int i = 0; i < 16; i++) {
                    int idx = tid + i * 256;
                    int code = idx >> 5, kk = idx & 31;
                    Bs[kk * 132 + code] =
                        E[(size_t)(seg0 + cb + code) * CDIM + c0 + kk];
                }
                __syncthreads();
#pragma unroll
                for (int kk = 0; kk < 32; kk++) {
                    const float* ar = As + (c0 + kk) * 68;
                    const float* br = Bs + kk * 132;
                    float4 a0 = *(const float4*)&ar[ty * 4];
                    ull aa[4] = {dup2(a0.x), dup2(a0.y), dup2(a0.z), dup2(a0.w)};
                    ulonglong2 b0 = *(const ulonglong2*)&br[tx * 4];
                    ulonglong2 b1 = *(const ulonglong2*)&br[64 + tx * 4];
                    ull bb[4] = {b0.x, b0.y, b1.x, b1.y};
#pragma unroll
                    for (int i = 0; i < 4; i++)
#pragma unroll
                        for (int j = 0; j < 4; j++) fma2(acc[i][j], aa[i], bb[j]);
                }
                __syncthreads();
            }
#pragma unroll
            for (int jh = 0; jh < 2; jh++) {
#pragma unroll
                for (int h = 0; h < 2; h++) {
                    int j2 = jh * 2 + h;
                    int col = seg0 + cb + jh * 64 + tx * 4 + h * 2;
                    float eq0 = esq[col], eq1 = esq[col + 1];
#pragma unroll
                    for (int i = 0; i < 4; i++) {
                        float2 pv = unpk2(acc[i][j2]);
                        float v0 = __fadd_rn(__fadd_rn(zrow[i], -__fmul_rn(2.f, pv.x)), eq0);
                        if (v0 < bestv[i]) { bestv[i] = v0; besti[i] = col; }
                        float v1 = __fadd_rn(__fadd_rn(zrow[i], -__fmul_rn(2.f, pv.y)), eq1);
                        if (v1 < bestv[i]) { bestv[i] = v1; besti[i] = col + 1; }
                    }
                }
            }
        }

#pragma unroll
        for (int i = 0; i < 4; i++) {
            float v = bestv[i]; int ix = besti[i];
#pragma unroll
            for (int off = 1; off <= 8; off <<= 1) {
                float ov = __shfl_xor_sync(0xffffffffu, v, off);
                int   oi = __shfl_xor_sync(0xffffffffu, ix, off);
                if (ov < v || (ov == v && oi < ix)) { v = ov; ix = oi; }
            }
            if (tx == 0 && rid[i] >= 0)
                atomicMin(&g_fbkey[rid[i]], dkey(v, ix));
        }
    }
}

// ============================================================================
// Gather: resolve nn; zq; residual; zq_sum; stage-3 straight-through;
// next-stage ||ze||^2 fused.
// ============================================================================
__global__ void gather_kernel(const float* __restrict__ ze,
                              const float* __restrict__ E,
                              float* __restrict__ zq_out,
                              float* __restrict__ ze_next,
                              float* __restrict__ nn_f,
                              const float* __restrict__ ze1,
                              int stage)
{
    __shared__ float buf[CDIM];
    int row = blockIdx.x, c = threadIdx.x;
    int idx = (g_p1v2[row] - g_p1v1[row] <= BAND)
                  ? (int)(unsigned)(g_fbkey[row] & 0xffffffffull)
                  : g_p1i1[row];

    float q = E[(size_t)idx * CDIM + c];
    size_t o = (size_t)row * CDIM + c;
    zq_out[o] = q;
    if (ze_next) {
        float zn = __fadd_rn(ze[o], -q);
        ze_next[o] = zn;
        buf[c] = zn;
    }
    float s = (stage == 0) ? q : __fadd_rn(g_zqsum[o], q);
    if (stage == 3) {
        float z1 = ze1[o];
        s = __fadd_rn(z1, __fadd_rn(s, -z1));
    }
    g_zqsum[o] = s;
    if (c == 0) nn_f[row] = (float)idx;

    if (ze_next) {
        __syncthreads();
        if (c == 0) {
            float acc = 0.f;
#pragma unroll 8
            for (int i = 0; i < CDIM; i++)
                acc = __fadd_rn(acc, __fmul_rn(buf[i], buf[i]));
            g_ze2[row] = acc;
        }
    }
}

// ============================================================================
// kernel_launch — output: x_hat | ze_1..4 | zq_1..4 | nn_1..4
// ============================================================================
extern "C" void kernel_launch(void* const* d_in, const int* in_sizes, int n_in,
                              void* d_out, int out_size)
{
    const float* x     = (const float*)d_in[0];
    const float* W_enc = (const float*)d_in[1];
    const float* b_enc = (const float*)d_in[2];
    const float* E[4]  = {(const float*)d_in[3], (const float*)d_in[4],
                          (const float*)d_in[5], (const float*)d_in[6]};
    const float* W_dec = (const float*)d_in[7];
    const float* b_dec = (const float*)d_in[8];

    float* out = (float*)d_out;
    const size_t NC     = (size_t)NROWS * CDIM;
    const size_t OFF_ZE = (size_t)NROWS * INDIM;
    const size_t OFF_ZQ = OFF_ZE + 4 * NC;
    const size_t OFF_NN = OFF_ZQ + 4 * NC;
    const float* ze1 = out + OFF_ZE;

    void* zqsum_ptr = nullptr;
    cudaGetSymbolAddress(&zqsum_ptr, g_zqsum);

    cudaFuncSetAttribute(vq_pass1_kernel,
                         cudaFuncAttributeMaxDynamicSharedMemorySize, P1_SMEM);
    cudaFuncSetAttribute(vq_fallback_kernel,
                         cudaFuncAttributeMaxDynamicSharedMemorySize, FB_SMEM);

    // one-time preprocessing
    esq4_kernel<<<dim3(KCODES / 32, 4), 256>>>(E[0], E[1], E[2], E[3]);
    pack_kernel<<<(4 * KCODES * 128) / 256, 256>>>(E[0], E[1], E[2], E[3]);

    // encoder
    sgemm_bias_kernel<<<dim3(CDIM / 128, NROWS / 128), 256>>>(
        x, W_enc, b_enc, out + OFF_ZE, NROWS, INDIM, CDIM);
    rownorm_kernel<<<NROWS / 32, 256>>>(out + OFF_ZE);

    // 4 sequential VQ stages
    for (int s = 0; s < 4; s++) {
        const float* zes = out + OFF_ZE + (size_t)s * NC;
        vq_pass1_kernel<<<NROWS / 128, 256, P1_SMEM>>>(zes, s);
        vq_fallback_kernel<<<dim3(32, 8), 256, FB_SMEM>>>(zes, E[s], s);
        float* zenext = (s < 3) ? (out + OFF_ZE + (size_t)(s + 1) * NC) : nullptr;
        gather_kernel<<<NROWS, 256>>>(zes, E[s],
                                      out + OFF_ZQ + (size_t)s * NC,
                                      zenext,
                                      out + OFF_NN + (size_t)s * NROWS,
                                      ze1, s);
    }

    // decoder
    sgemm_bias_kernel<<<dim3(INDIM / 128, NROWS / 128), 256>>>(
        (const float*)zqsum_ptr, W_dec, b_dec, out, NROWS, CDIM, INDIM);
}

// round 13
// speedup vs baseline: 2.0254x; 1.0348x over previous
#include <cuda_runtime.h>
#include <cuda_bf16.h>
#include <cstddef>
#include <cstdint>

#define NROWS 16384
#define INDIM 768
#define CDIM  256
#define KCODES 4096
#define BAND  8e-3f

typedef unsigned long long ull;

// ---- device scratch ----
__device__ float g_zqsum[NROWS * CDIM];
__device__ float g_esq[4][KCODES];
__device__ float g_ze2[NROWS];
__device__ float g_p1v1[NROWS];
__device__ float g_p1v2[NROWS];
__device__ int   g_p1i1[NROWS];
__device__ ull   g_fbkey[NROWS];
__device__ int   g_fbcount[4];
__device__ int   g_fbrows[NROWS];
// codebook bf16 planes, TILE-SWIZZLED layout:
//   tile = code>>5 (128 tiles of 32 codes), row = code&31, word = c>>1
//   elem offset = tile*8192 + row*256 + ((word ^ ((row&7)<<2)) << 1) + (c&1)
// -> 16B blocks permuted as blk ^ (row&7); each tile 16KB contiguous.
__device__ __nv_bfloat16 g_PBh[4][KCODES * CDIM];
__device__ __nv_bfloat16 g_PBl[4][KCODES * CDIM];

// ---- helpers ----
__device__ __forceinline__ void fma2(ull& d, ull a, ull b)
{ asm("fma.rn.f32x2 %0, %1, %2, %0;" : "+l"(d) : "l"(a), "l"(b)); }
__device__ __forceinline__ ull dup2(float x)
{ ull r; asm("mov.b64 %0, {%1, %1};" : "=l"(r) : "f"(x)); return r; }
__device__ __forceinline__ float2 unpk2(ull v)
{ float2 r; asm("mov.b64 {%0, %1}, %2;" : "=f"(r.x), "=f"(r.y) : "l"(v)); return r; }
__device__ __forceinline__ void mma16816(float* d, const uint32_t* a,
                                         uint32_t b0, uint32_t b1)
{
    asm volatile(
        "mma.sync.aligned.m16n8k16.row.col.f32.bf16.bf16.f32 "
        "{%0,%1,%2,%3}, {%4,%5,%6,%7}, {%8,%9}, {%0,%1,%2,%3};"
        : "+f"(d[0]), "+f"(d[1]), "+f"(d[2]), "+f"(d[3])
        : "r"(a[0]), "r"(a[1]), "r"(a[2]), "r"(a[3]), "r"(b0), "r"(b1));
}
__device__ __forceinline__ void ldsm4(uint32_t& r0, uint32_t& r1,
                                      uint32_t& r2, uint32_t& r3, uint32_t a)
{
    asm volatile("ldmatrix.sync.aligned.m8n8.x4.shared.b16 {%0,%1,%2,%3}, [%4];"
                 : "=r"(r0), "=r"(r1), "=r"(r2), "=r"(r3) : "r"(a));
}
__device__ __forceinline__ ull dkey(float d, int code)
{
    uint32_t u = __float_as_uint(d);
    u = (u >> 31) ? ~u : (u | 0x80000000u);
    return ((ull)u << 32) | (unsigned)code;
}
__device__ __forceinline__ void mbar_init(uint32_t a)
{ asm volatile("mbarrier.init.shared.b64 [%0], 1;" :: "r"(a) : "memory"); }
__device__ __forceinline__ void mbar_expect(uint32_t a, uint32_t bytes)
{ asm volatile("mbarrier.arrive.expect_tx.shared.b64 _, [%0], %1;" :: "r"(a), "r"(bytes) : "memory"); }
__device__ __forceinline__ void mbar_wait(uint32_t a, int phase)
{
    asm volatile(
        "{\n\t.reg .pred p;\n"
        "L%=:\n\t"
        "mbarrier.try_wait.parity.acquire.cta.shared::cta.b64 p, [%0], %1;\n\t"
        "@!p bra L%=;\n\t}"
        :: "r"(a), "r"(phase) : "memory");
}
__device__ __forceinline__ void bulk_cp(uint32_t dst, const void* src,
                                        uint32_t bytes, uint32_t mbar)
{
    asm volatile(
        "cp.async.bulk.shared::cta.global.mbarrier::complete_tx::bytes "
        "[%0], [%1], %2, [%3];"
        :: "r"(dst), "l"(src), "r"(bytes), "r"(mbar) : "memory");
}

// ============================================================================
// exact fp32 SGEMM + bias via packed f32x2 (bit-matches reference)
// ============================================================================
__global__ __launch_bounds__(256) void sgemm_bias_kernel(
    const float* __restrict__ A, const float* __restrict__ B,
    const float* __restrict__ bias, float* __restrict__ C,
    int M, int Kd, int Nn)
{
    __shared__ __align__(16) float As[32][132];
    __shared__ __align__(16) float Bs[32][132];
    const int tid = threadIdx.x, tx = tid & 15, ty = tid >> 4;
    const int m0 = blockIdx.y * 128, n0 = blockIdx.x * 128;

    ull acc[8][4];
#pragma unroll
    for (int i = 0; i < 8; i++)
#pragma unroll
        for (int j = 0; j < 4; j++) acc[i][j] = 0ull;

    for (int k0 = 0; k0 < Kd; k0 += 32) {
#pragma unroll
        for (int i = 0; i < 16; i++) {
            int idx = tid + i * 256, mm = idx >> 5, kk = idx & 31;
            As[kk][mm] = A[(size_t)(m0 + mm) * Kd + (k0 + kk)];
        }
#pragma unroll
        for (int i = 0; i < 16; i++) {
            int idx = tid + i * 256, kk = idx >> 7, nn = idx & 127;
            Bs[kk][nn] = B[(size_t)(k0 + kk) * Nn + (n0 + nn)];
        }
        __syncthreads();
#pragma unroll
        for (int kk = 0; kk < 32; kk++) {
            float4 a0 = *(const float4*)&As[kk][ty * 4];
            float4 a1 = *(const float4*)&As[kk][64 + ty * 4];
            ull aa[8] = {dup2(a0.x), dup2(a0.y), dup2(a0.z), dup2(a0.w),
                         dup2(a1.x), dup2(a1.y), dup2(a1.z), dup2(a1.w)};
            ulonglong2 b0 = *(const ulonglong2*)&Bs[kk][tx * 4];
            ulonglong2 b1 = *(const ulonglong2*)&Bs[kk][64 + tx * 4];
            ull bb[4] = {b0.x, b0.y, b1.x, b1.y};
#pragma unroll
            for (int i = 0; i < 8; i++)
#pragma unroll
                for (int j = 0; j < 4; j++) fma2(acc[i][j], aa[i], bb[j]);
        }
        __syncthreads();
    }
#pragma unroll
    for (int i = 0; i < 8; i++) {
        int row = m0 + ((i < 4) ? (ty * 4 + i) : (64 + ty * 4 + (i - 4)));
#pragma unroll
        for (int jh = 0; jh < 2; jh++) {
            int col = n0 + (jh ? (64 + tx * 4) : (tx * 4));
            float2 p0 = unpk2(acc[i][jh * 2 + 0]);
            float2 p1 = unpk2(acc[i][jh * 2 + 1]);
            float4 v;
            v.x = __fadd_rn(p0.x, bias[col + 0]);
            v.y = __fadd_rn(p0.y, bias[col + 1]);
            v.z = __fadd_rn(p1.x, bias[col + 2]);
            v.w = __fadd_rn(p1.y, bias[col + 3]);
            *(float4*)&C[(size_t)row * Nn + col] = v;
        }
    }
}

// ============================================================================
// pack codebooks into tile-swizzled bf16 hi/lo planes + zero fb counters
// ============================================================================
__global__ void pack_kernel(const float* __restrict__ E0,
                            const float* __restrict__ E1,
                            const float* __restrict__ E2,
                            const float* __restrict__ E3)
{
    int gid = blockIdx.x * 256 + threadIdx.x;
    if (gid < 4) g_fbcount[gid] = 0;
    int stage = gid >> 19;
    int rem = gid & 524287;
    int code = rem >> 7, word = rem & 127;
    const float* E = (stage == 0) ? E0 : (stage == 1) ? E1 : (stage == 2) ? E2 : E3;
    float f0 = E[(size_t)code * CDIM + word * 2];
    float f1 = E[(size_t)code * CDIM + word * 2 + 1];
    __nv_bfloat16 h0 = __float2bfloat16(f0);
    __nv_bfloat16 h1 = __float2bfloat16(f1);
    __nv_bfloat16 l0 = __float2bfloat16(f0 - __bfloat162float(h0));
    __nv_bfloat16 l1 = __float2bfloat16(f1 - __bfloat162float(h1));
    int tile = code >> 5, row = code & 31;
    int off = tile * 8192 + row * 256 + ((word ^ ((row & 7) << 2)) << 1);
    g_PBh[stage][off] = h0; g_PBh[stage][off + 1] = h1;
    g_PBl[stage][off] = l0; g_PBl[stage][off + 1] = l1;
}

// ============================================================================
// ||E_k||^2 (exact sequential XLA chain), coalesced via smem staging
// ============================================================================
__global__ __launch_bounds__(256) void esq4_kernel(
    const float* __restrict__ E0, const float* __restrict__ E1,
    const float* __restrict__ E2, const float* __restrict__ E3)
{
    __shared__ float s[32][257];
    int stage = blockIdx.y;
    const float* E = (stage == 0) ? E0 : (stage == 1) ? E1 : (stage == 2) ? E2 : E3;
    int row0 = blockIdx.x * 32, tid = threadIdx.x;
#pragma unroll
    for (int i = 0; i < 32; i++) {
        int idx = tid + i * 256, r = idx >> 8, c = idx & 255;
        s[r][c] = E[(size_t)(row0 + r) * CDIM + c];
    }
    __syncthreads();
    if (tid < 32) {
        float acc = 0.f;
#pragma unroll 8
        for (int c = 0; c < CDIM; c++) {
            float v = s[tid][c];
            acc = __fadd_rn(acc, __fmul_rn(v, v));
        }
        g_esq[stage][row0 + tid] = acc;
    }
}

// ============================================================================
// ||ze||^2 (stage 0 only; later stages fused into gather)
// ============================================================================
__global__ __launch_bounds__(256) void rownorm_kernel(const float* __restrict__ ze)
{
    __shared__ float s[32][257];
    int row0 = blockIdx.x * 32, tid = threadIdx.x;
#pragma unroll
    for (int i = 0; i < 32; i++) {
        int idx = tid + i * 256, r = idx >> 8, c = idx & 255;
        s[r][c] = ze[(size_t)(row0 + r) * CDIM + c];
    }
    __syncthreads();
    if (tid < 32) {
        float acc = 0.f;
#pragma unroll 8
        for (int c = 0; c < CDIM; c++) {
            float v = s[tid][c];
            acc = __fadd_rn(acc, __fmul_rn(v, v));
        }
        g_ze2[row0 + tid] = acc;
    }
}

// ============================================================================
// PASS 1: bf16 hi/lo HMMA screening; bulk-copied B tiles; ldmatrix fragment
// loads (4x fewer shared-load issues than scalar LDS; same decisions).
// 256 thr (8 warps), 128 rows/CTA; 128 chunks of 32 codes (dbuf, mbarrier).
// ============================================================================
#define P1_ASTR 264
#define P1_BOFF 135168
#define P1_SMEM (135168 + 65536)

__global__ __launch_bounds__(256, 1) void vq_pass1_kernel(
    const float* __restrict__ ze, int stage)
{
    extern __shared__ char smc[];
    __nv_bfloat16* Ah = (__nv_bfloat16*)(smc);
    __nv_bfloat16* Al = (__nv_bfloat16*)(smc + 67584);
    __shared__ __align__(8) ull mbar[2];

    const int tid = threadIdx.x;
    const int w = tid >> 5, lane = tid & 31;
    const int g = lane >> 2, tig = lane & 3;
    const int row0 = blockIdx.x * 128;
    const float* __restrict__ esq = g_esq[stage];
    const __nv_bfloat16* __restrict__ PBh = g_PBh[stage];
    const __nv_bfloat16* __restrict__ PBl = g_PBl[stage];
    const uint32_t sb = (uint32_t)__cvta_generic_to_shared(smc);
    const uint32_t mb0 = (uint32_t)__cvta_generic_to_shared(&mbar[0]);
    const uint32_t mb1 = (uint32_t)__cvta_generic_to_shared(&mbar[1]);

    if (tid == 0) { mbar_init(mb0); mbar_init(mb1); }
    __syncthreads();

    // prefetch chunk 0 into buffer 0 (hi 16KB + lo 16KB)
    if (tid == 0) {
        mbar_expect(mb0, 32768u);
        bulk_cp(sb + P1_BOFF, PBh, 16384u, mb0);
        bulk_cp(sb + P1_BOFF + 16384u, PBl, 16384u, mb0);
    }

    // fill persistent A planes (split ze into bf16 hi+lo)
#pragma unroll 4
    for (int i = 0; i < 32; i++) {
        int idx = tid + i * 256;
        int r = idx >> 6, c4 = idx & 63;
        float4 f = *(const float4*)(ze + (size_t)(row0 + r) * CDIM + c4 * 4);
        __nv_bfloat162 h01, h23, l01, l23;
        h01.x = __float2bfloat16(f.x); l01.x = __float2bfloat16(f.x - __bfloat162float(h01.x));
        h01.y = __float2bfloat16(f.y); l01.y = __float2bfloat16(f.y - __bfloat162float(h01.y));
        h23.x = __float2bfloat16(f.z); l23.x = __float2bfloat16(f.z - __bfloat162float(h23.x));
        h23.y = __float2bfloat16(f.w); l23.y = __float2bfloat16(f.w - __bfloat162float(h23.y));
        int o = r * P1_ASTR + c4 * 4;
        *(__nv_bfloat162*)(Ah + o) = h01; *(__nv_bfloat162*)(Ah + o + 2) = h23;
        *(__nv_bfloat162*)(Al + o) = l01; *(__nv_bfloat162*)(Al + o + 2) = l23;
    }

    float m1[2] = {3.4e38f, 3.4e38f}, m2[2] = {3.4e38f, 3.4e38f};
    int   i1[2] = {0, 0};

    // ldmatrix lane pointers:
    // A x4: row = lane&15 (of warp's 16), k-half = lane>>4
    const uint32_t a_off =
        (uint32_t)(((w * 16 + (lane & 15)) * P1_ASTR + ((lane >> 4) << 3)) * 2);
    const uint32_t ah_base = sb + a_off;
    const uint32_t al_base = sb + 67584u + a_off;
    // B x4 (one per nt-pair): n-row in pair = (lane>>4)*8 + (lane&7),
    // k-block bit = (lane>>3)&1, swizzle XOR uses lane&7.
    const uint32_t brow512 = (uint32_t)((((lane >> 4) << 3) + (lane & 7)) * 512);
    const int kb = (lane >> 3) & 1;
    const int bx = lane & 7;

    for (int t = 0; t < 128; t++) {
        mbar_wait((t & 1) ? mb1 : mb0, (t >> 1) & 1);
        __syncthreads();   // all warps done with the OTHER buffer's compute

        if (t < 127 && tid == 0) {
            const uint32_t dst = sb + P1_BOFF + ((t + 1) & 1) * 32768u;
            const uint32_t mb = ((t + 1) & 1) ? mb1 : mb0;
            const size_t so = (size_t)(t + 1) * 8192;
            mbar_expect(mb, 32768u);
            bulk_cp(dst, PBh + so, 16384u, mb);
            bulk_cp(dst + 16384u, PBl + so, 16384u, mb);
        }

        const uint32_t Bhi = sb + P1_BOFF + (uint32_t)((t & 1) * 32768);
        const uint32_t Blo = Bhi + 16384u;

        float acc[4][4];
#pragma unroll
        for (int nt = 0; nt < 4; nt++)
#pragma unroll
            for (int j = 0; j < 4; j++) acc[nt][j] = 0.f;

#pragma unroll 8
        for (int k = 0; k < 16; k++) {
            uint32_t ah[4], al[4];
            ldsm4(ah[0], ah[1], ah[2], ah[3], ah_base + (uint32_t)(k * 32));
            ldsm4(al[0], al[1], al[2], al[3], al_base + (uint32_t)(k * 32));

            const uint32_t blk = (uint32_t)((((k << 1) | kb) ^ bx) << 4);
            uint32_t bh0[4], bh1[4], bl0[4], bl1[4];
            ldsm4(bh0[0], bh0[1], bh0[2], bh0[3], Bhi + brow512 + blk);
            ldsm4(bh1[0], bh1[1], bh1[2], bh1[3], Bhi + 8192u + brow512 + blk);
            ldsm4(bl0[0], bl0[1], bl0[2], bl0[3], Blo + brow512 + blk);
            ldsm4(bl1[0], bl1[1], bl1[2], bl1[3], Blo + 8192u + brow512 + blk);

            // hi*hi
            mma16816(acc[0], ah, bh0[0], bh0[1]);
            mma16816(acc[1], ah, bh0[2], bh0[3]);
            mma16816(acc[2], ah, bh1[0], bh1[1]);
            mma16816(acc[3], ah, bh1[2], bh1[3]);
            // hi*lo
            mma16816(acc[0], ah, bl0[0], bl0[1]);
            mma16816(acc[1], ah, bl0[2], bl0[3]);
            mma16816(acc[2], ah, bl1[0], bl1[1]);
            mma16816(acc[3], ah, bl1[2], bl1[3]);
            // lo*hi
            mma16816(acc[0], al, bh0[0], bh0[1]);
            mma16816(acc[1], al, bh0[2], bh0[3]);
            mma16816(acc[2], al, bh1[0], bh1[1]);
            mma16816(acc[3], al, bh1[2], bh1[3]);
        }

        // epilogue: per-thread min1/min2 over this chunk's codes
        const int code0 = t * 32;
#pragma unroll
        for (int nt = 0; nt < 4; nt++) {
            int c0 = code0 + nt * 8 + 2 * tig;
            float e0 = esq[c0], e1 = esq[c0 + 1];
#pragma unroll
            for (int s = 0; s < 2; s++) {       // s=0: row g, s=1: row g+8
                float d0 = fmaf(-2.f, acc[nt][s * 2 + 0], e0);
                if (d0 < m1[s]) { m2[s] = m1[s]; m1[s] = d0; i1[s] = c0; }
                else if (d0 < m2[s]) m2[s] = d0;
                float d1 = fmaf(-2.f, acc[nt][s * 2 + 1], e1);
                if (d1 < m1[s]) { m2[s] = m1[s]; m1[s] = d1; i1[s] = c0 + 1; }
                else if (d1 < m2[s]) m2[s] = d1;
            }
        }
    }

    // merge across the 4 tig lanes sharing each row
#pragma unroll
    for (int s = 0; s < 2; s++) {
#pragma unroll
        for (int off = 1; off <= 2; off <<= 1) {
            float o1 = __shfl_xor_sync(0xffffffffu, m1[s], off);
            int   oi = __shfl_xor_sync(0xffffffffu, i1[s], off);
            float o2 = __shfl_xor_sync(0xffffffffu, m2[s], off);
            float nm2 = fminf(fmaxf(m1[s], o1), fminf(m2[s], o2));
            if (o1 < m1[s] || (o1 == m1[s] && oi < i1[s])) { m1[s] = o1; i1[s] = oi; }
            m2[s] = nm2;
        }
    }
    if (tig == 0) {
#pragma unroll
        for (int s = 0; s < 2; s++) {
            int row = row0 + w * 16 + g + s * 8;
            g_p1v1[row] = m1[s];
            g_p1v2[row] = m2[s];
            g_p1i1[row] = i1[s];
            g_fbkey[row] = ~0ull;
            if (m2[s] - m1[s] <= BAND) {
                int pos = atomicAdd(&g_fbcount[stage], 1);
                g_fbrows[pos] = row;
            }
        }
    }
}

// ============================================================================
// PASS 2: exact fallback (exact reference arithmetic + atomicMin on monotone
// key -> exact argmin, lowest-index ties).
// ============================================================================
#define FB_SMEM ((256 * 68 + 32 * 132) * 4 + 256)

__global__ __launch_bounds__(256) void vq_fallback_kernel(
    const float* __restrict__ ze, const float* __restrict__ E, int stage)
{
    extern __shared__ __align__(16) float fsm[];
    float* As = fsm;
    float* Bs = fsm + 256 * 68;
    int* rowsm = (int*)(fsm + 256 * 68 + 32 * 132);

    const int cnt = g_fbcount[stage];
    const int tid = threadIdx.x, tx = tid & 15, ty = tid >> 4;
    const int seg0 = blockIdx.y * 512;
    const float* __restrict__ esq = g_esq[stage];

    for (int base = blockIdx.x * 64; base < cnt; base += gridDim.x * 64) {
        __syncthreads();
        if (tid < 64) rowsm[tid] = (base + tid < cnt) ? g_fbrows[base + tid] : -1;
        __syncthreads();
#pragma unroll 4
        for (int i = 0; i < 64; i++) {
            int idx = tid + i * 256;
            int r = idx >> 8, c = idx & 255;
            int rr = rowsm[r];
            As[c * 68 + r] = (rr >= 0) ? ze[(size_t)rr * CDIM + c] : 0.f;
        }
        float zrow[4]; int rid[4];
#pragma unroll
        for (int i = 0; i < 4; i++) {
            rid[i] = rowsm[ty * 4 + i];
            zrow[i] = (rid[i] >= 0) ? g_ze2[rid[i]] : 0.f;
        }
        float bestv[4]; int besti[4];
#pragma unroll
        for (int i = 0; i < 4; i++) { bestv[i] = 3.4e38f; besti[i] = 0; }
        __syncthreads();

        for (int cb = 0; cb < 512; cb += 128) {
            ull acc[4][4];
#pragma unroll
            for (int i = 0; i < 4; i++)
#pragma unroll
                for (int j = 0; j < 4; j++) acc[i][j] = 0ull;

            for (int c0 = 0; c0 < CDIM; c0 += 32) {
#pragma unroll
                for (int i = 0; i < 16; i++) {
                    int idx = tid + i * 256;
                    int code = idx >> 5, kk = idx & 31;
                    Bs[kk * 132 + code] =
                        E[(size_t)(seg0 + cb + code) * CDIM + c0 + kk];
                }
                __syncthreads();
#pragma unroll
                for (int kk = 0; kk < 32; kk++) {
                    const float* ar = As + (c0 + kk) * 68;
                    const float* br = Bs + kk * 132;
                    float4 a0 = *(const float4*)&ar[ty * 4];
                    ull aa[4] = {dup2(a0.x), dup2(a0.y), dup2(a0.z), dup2(a0.w)};
                    ulonglong2 b0 = *(const ulonglong2*)&br[tx * 4];
                    ulonglong2 b1 = *(const ulonglong2*)&br[64 + tx * 4];
                    ull bb[4] = {b0.x, b0.y, b1.x, b1.y};
#pragma unroll
                    for (int i = 0; i < 4; i++)
#pragma unroll
                        for (int j = 0; j < 4; j++) fma2(acc[i][j], aa[i], bb[j]);
                }
                __syncthreads();
            }
#pragma unroll
            for (int jh = 0; jh < 2; jh++) {
#pragma unroll
                for (int h = 0; h < 2; h++) {
                    int j2 = jh * 2 + h;
                    int col = seg0 + cb + jh * 64 + tx * 4 + h * 2;
                    float eq0 = esq[col], eq1 = esq[col + 1];
#pragma unroll
                    for (int i = 0; i < 4; i++) {
                        float2 pv = unpk2(acc[i][j2]);
                        float v0 = __fadd_rn(__fadd_rn(zrow[i], -__fmul_rn(2.f, pv.x)), eq0);
                        if (v0 < bestv[i]) { bestv[i] = v0; besti[i] = col; }
                        float v1 = __fadd_rn(__fadd_rn(zrow[i], -__fmul_rn(2.f, pv.y)), eq1);
                        if (v1 < bestv[i]) { bestv[i] = v1; besti[i] = col + 1; }
                    }
                }
            }
        }

#pragma unroll
        for (int i = 0; i < 4; i++) {
            float v = bestv[i]; int ix = besti[i];
#pragma unroll
            for (int off = 1; off <= 8; off <<= 1) {
                float ov = __shfl_xor_sync(0xffffffffu, v, off);
                int   oi = __shfl_xor_sync(0xffffffffu, ix, off);
                if (ov < v || (ov == v && oi < ix)) { v = ov; ix = oi; }
            }
            if (tx == 0 && rid[i] >= 0)
                atomicMin(&g_fbkey[rid[i]], dkey(v, ix));
        }
    }
}

// ============================================================================
// Gather: resolve nn; zq; residual; zq_sum; stage-3 straight-through;
// next-stage ||ze||^2 fused.
// ============================================================================
__global__ void gather_kernel(const float* __restrict__ ze,
                              const float* __restrict__ E,
                              float* __restrict__ zq_out,
                              float* __restrict__ ze_next,
                              float* __restrict__ nn_f,
                              const float* __restrict__ ze1,
                              int stage)
{
    __shared__ float buf[CDIM];
    int row = blockIdx.x, c = threadIdx.x;
    int idx = (g_p1v2[row] - g_p1v1[row] <= BAND)
                  ? (int)(unsigned)(g_fbkey[row] & 0xffffffffull)
                  : g_p1i1[row];

    float q = E[(size_t)idx * CDIM + c];
    size_t o = (size_t)row * CDIM + c;
    zq_out[o] = q;
    if (ze_next) {
        float zn = __fadd_rn(ze[o], -q);
        ze_next[o] = zn;
        buf[c] = zn;
    }
    float s = (stage == 0) ? q : __fadd_rn(g_zqsum[o], q);
    if (stage == 3) {
        float z1 = ze1[o];
        s = __fadd_rn(z1, __fadd_rn(s, -z1));
    }
    g_zqsum[o] = s;
    if (c == 0) nn_f[row] = (float)idx;

    if (ze_next) {
        __syncthreads();
        if (c == 0) {
            float acc = 0.f;
#pragma unroll 8
            for (int i = 0; i < CDIM; i++)
                acc = __fadd_rn(acc, __fmul_rn(buf[i], buf[i]));
            g_ze2[row] = acc;
        }
    }
}

// ============================================================================
// kernel_launch — output: x_hat | ze_1..4 | zq_1..4 | nn_1..4
// ============================================================================
extern "C" void kernel_launch(void* const* d_in, const int* in_sizes, int n_in,
                              void* d_out, int out_size)
{
    const float* x     = (const float*)d_in[0];
    const float* W_enc = (const float*)d_in[1];
    const float* b_enc = (const float*)d_in[2];
    const float* E[4]  = {(const float*)d_in[3], (const float*)d_in[4],
                          (const float*)d_in[5], (const float*)d_in[6]};
    const float* W_dec = (const float*)d_in[7];
    const float* b_dec = (const float*)d_in[8];

    float* out = (float*)d_out;
    const size_t NC     = (size_t)NROWS * CDIM;
    const size_t OFF_ZE = (size_t)NROWS * INDIM;
    const size_t OFF_ZQ = OFF_ZE + 4 * NC;
    const size_t OFF_NN = OFF_ZQ + 4 * NC;
    const float* ze1 = out + OFF_ZE;

    void* zqsum_ptr = nullptr;
    cudaGetSymbolAddress(&zqsum_ptr, g_zqsum);

    cudaFuncSetAttribute(vq_pass1_kernel,
                         cudaFuncAttributeMaxDynamicSharedMemorySize, P1_SMEM);
    cudaFuncSetAttribute(vq_fallback_kernel,
                         cudaFuncAttributeMaxDynamicSharedMemorySize, FB_SMEM);

    // one-time preprocessing
    esq4_kernel<<<dim3(KCODES / 32, 4), 256>>>(E[0], E[1], E[2], E[3]);
    pack_kernel<<<(4 * KCODES * 128) / 256, 256>>>(E[0], E[1], E[2], E[3]);

    // encoder
    sgemm_bias_kernel<<<dim3(CDIM / 128, NROWS / 128), 256>>>(
        x, W_enc, b_enc, out + OFF_ZE, NROWS, INDIM, CDIM);
    rownorm_kernel<<<NROWS / 32, 256>>>(out + OFF_ZE);

    // 4 sequential VQ stages
    for (int s = 0; s < 4; s++) {
        const float* zes = out + OFF_ZE + (size_t)s * NC;
        vq_pass1_kernel<<<NROWS / 128, 256, P1_SMEM>>>(zes, s);
        vq_fallback_kernel<<<dim3(32, 8), 256, FB_SMEM>>>(zes, E[s], s);
        float* zenext = (s < 3) ? (out + OFF_ZE + (size_t)(s + 1) * NC) : nullptr;
        gather_kernel<<<NROWS, 256>>>(zes, E[s],
                                      out + OFF_ZQ + (size_t)s * NC,
                                      zenext,
                                      out + OFF_NN + (size_t)s * NROWS,
                                      ze1, s);
    }

    // decoder
    sgemm_bias_kernel<<<dim3(INDIM / 128, NROWS / 128), 256>>>(
        (const float*)zqsum_ptr, W_dec, b_dec, out, NROWS, CDIM, INDIM);
}

// round 15
// speedup vs baseline: 2.2617x; 1.1167x over previous
#include <cuda_runtime.h>
#include <cuda_fp16.h>
#include <cstddef>
#include <cstdint>

#define NROWS 16384
#define INDIM 768
#define CDIM  256
#define KCODES 4096
#define BAND  1.2e-2f

typedef unsigned long long ull;

// ---- device scratch ----
__device__ float g_zqsum[NROWS * CDIM];
__device__ float g_esq[4][KCODES];
__device__ float g_ze2[NROWS];
__device__ float g_p1v1[NROWS];
__device__ float g_p1v2[NROWS];
__device__ int   g_p1i1[NROWS];
__device__ ull   g_fbkey[NROWS];
__device__ int   g_fbcount[4];
__device__ int   g_fbrows[NROWS];
// codebook fp16 plane, TILE-SWIZZLED layout:
//   tile = code>>5 (128 tiles of 32 codes), row = code&31, word = c>>1
//   elem offset = tile*8192 + row*256 + ((word ^ ((row&7)<<2)) << 1) + (c&1)
// -> 16B blocks permuted as blk ^ (row&7); each tile 16KB contiguous.
__device__ __half g_PB[4][KCODES * CDIM];

// ---- helpers ----
__device__ __forceinline__ void fma2(ull& d, ull a, ull b)
{ asm("fma.rn.f32x2 %0, %1, %2, %0;" : "+l"(d) : "l"(a), "l"(b)); }
__device__ __forceinline__ ull dup2(float x)
{ ull r; asm("mov.b64 %0, {%1, %1};" : "=l"(r) : "f"(x)); return r; }
__device__ __forceinline__ float2 unpk2(ull v)
{ float2 r; asm("mov.b64 {%0, %1}, %2;" : "=f"(r.x), "=f"(r.y) : "l"(v)); return r; }
__device__ __forceinline__ void mma16816h(float* d, const uint32_t* a,
                                          uint32_t b0, uint32_t b1)
{
    asm volatile(
        "mma.sync.aligned.m16n8k16.row.col.f32.f16.f16.f32 "
        "{%0,%1,%2,%3}, {%4,%5,%6,%7}, {%8,%9}, {%0,%1,%2,%3};"
        : "+f"(d[0]), "+f"(d[1]), "+f"(d[2]), "+f"(d[3])
        : "r"(a[0]), "r"(a[1]), "r"(a[2]), "r"(a[3]), "r"(b0), "r"(b1));
}
__device__ __forceinline__ void ldsm4(uint32_t& r0, uint32_t& r1,
                                      uint32_t& r2, uint32_t& r3, uint32_t a)
{
    asm volatile("ldmatrix.sync.aligned.m8n8.x4.shared.b16 {%0,%1,%2,%3}, [%4];"
                 : "=r"(r0), "=r"(r1), "=r"(r2), "=r"(r3) : "r"(a));
}
__device__ __forceinline__ ull dkey(float d, int code)
{
    uint32_t u = __float_as_uint(d);
    u = (u >> 31) ? ~u : (u | 0x80000000u);
    return ((ull)u << 32) | (unsigned)code;
}
__device__ __forceinline__ void mbar_init(uint32_t a)
{ asm volatile("mbarrier.init.shared.b64 [%0], 1;" :: "r"(a) : "memory"); }
__device__ __forceinline__ void mbar_expect(uint32_t a, uint32_t bytes)
{ asm volatile("mbarrier.arrive.expect_tx.shared.b64 _, [%0], %1;" :: "r"(a), "r"(bytes) : "memory"); }
__device__ __forceinline__ void mbar_wait(uint32_t a, int phase)
{
    asm volatile(
        "{\n\t.reg .pred p;\n"
        "L%=:\n\t"
        "mbarrier.try_wait.parity.acquire.cta.shared::cta.b64 p, [%0], %1;\n\t"
        "@!p bra L%=;\n\t}"
        :: "r"(a), "r"(phase) : "memory");
}
__device__ __forceinline__ void bulk_cp(uint32_t dst, const void* src,
                                        uint32_t bytes, uint32_t mbar)
{
    asm volatile(
        "cp.async.bulk.shared::cta.global.mbarrier::complete_tx::bytes "
        "[%0], [%1], %2, [%3];"
        :: "r"(dst), "l"(src), "r"(bytes), "r"(mbar) : "memory");
}

// ============================================================================
// exact fp32 SGEMM + bias via packed f32x2 (bit-matches reference)
// ============================================================================
__global__ __launch_bounds__(256) void sgemm_bias_kernel(
    const float* __restrict__ A, const float* __restrict__ B,
    const float* __restrict__ bias, float* __restrict__ C,
    int M, int Kd, int Nn)
{
    __shared__ __align__(16) float As[32][132];
    __shared__ __align__(16) float Bs[32][132];
    const int tid = threadIdx.x, tx = tid & 15, ty = tid >> 4;
    const int m0 = blockIdx.y * 128, n0 = blockIdx.x * 128;

    ull acc[8][4];
#pragma unroll
    for (int i = 0; i < 8; i++)
#pragma unroll
        for (int j = 0; j < 4; j++) acc[i][j] = 0ull;

    for (int k0 = 0; k0 < Kd; k0 += 32) {
#pragma unroll
        for (int i = 0; i < 16; i++) {
            int idx = tid + i * 256, mm = idx >> 5, kk = idx & 31;
            As[kk][mm] = A[(size_t)(m0 + mm) * Kd + (k0 + kk)];
        }
#pragma unroll
        for (int i = 0; i < 16; i++) {
            int idx = tid + i * 256, kk = idx >> 7, nn = idx & 127;
            Bs[kk][nn] = B[(size_t)(k0 + kk) * Nn + (n0 + nn)];
        }
        __syncthreads();
#pragma unroll
        for (int kk = 0; kk < 32; kk++) {
            float4 a0 = *(const float4*)&As[kk][ty * 4];
            float4 a1 = *(const float4*)&As[kk][64 + ty * 4];
            ull aa[8] = {dup2(a0.x), dup2(a0.y), dup2(a0.z), dup2(a0.w),
                         dup2(a1.x), dup2(a1.y), dup2(a1.z), dup2(a1.w)};
            ulonglong2 b0 = *(const ulonglong2*)&Bs[kk][tx * 4];
            ulonglong2 b1 = *(const ulonglong2*)&Bs[kk][64 + tx * 4];
            ull bb[4] = {b0.x, b0.y, b1.x, b1.y};
#pragma unroll
            for (int i = 0; i < 8; i++)
#pragma unroll
                for (int j = 0; j < 4; j++) fma2(acc[i][j], aa[i], bb[j]);
        }
        __syncthreads();
    }
#pragma unroll
    for (int i = 0; i < 8; i++) {
        int row = m0 + ((i < 4) ? (ty * 4 + i) : (64 + ty * 4 + (i - 4)));
#pragma unroll
        for (int jh = 0; jh < 2; jh++) {
            int col = n0 + (jh ? (64 + tx * 4) : (tx * 4));
            float2 p0 = unpk2(acc[i][jh * 2 + 0]);
            float2 p1 = unpk2(acc[i][jh * 2 + 1]);
            float4 v;
            v.x = __fadd_rn(p0.x, bias[col + 0]);
            v.y = __fadd_rn(p0.y, bias[col + 1]);
            v.z = __fadd_rn(p1.x, bias[col + 2]);
            v.w = __fadd_rn(p1.y, bias[col + 3]);
            *(float4*)&C[(size_t)row * Nn + col] = v;
        }
    }
}

// ============================================================================
// pack codebooks into tile-swizzled fp16 plane + zero fb counters
// ============================================================================
__global__ void pack_kernel(const float* __restrict__ E0,
                            const float* __restrict__ E1,
                            const float* __restrict__ E2,
                            const float* __restrict__ E3)
{
    int gid = blockIdx.x * 256 + threadIdx.x;
    if (gid < 4) g_fbcount[gid] = 0;
    int stage = gid >> 19;
    int rem = gid & 524287;
    int code = rem >> 7, word = rem & 127;
    const float* E = (stage == 0) ? E0 : (stage == 1) ? E1 : (stage == 2) ? E2 : E3;
    float f0 = E[(size_t)code * CDIM + word * 2];
    float f1 = E[(size_t)code * CDIM + word * 2 + 1];
    int tile = code >> 5, row = code & 31;
    int off = tile * 8192 + row * 256 + ((word ^ ((row & 7) << 2)) << 1);
    g_PB[stage][off] = __float2half(f0);
    g_PB[stage][off + 1] = __float2half(f1);
}

// ============================================================================
// ||E_k||^2 (exact sequential XLA chain), coalesced via smem staging
// ============================================================================
__global__ __launch_bounds__(256) void esq4_kernel(
    const float* __restrict__ E0, const float* __restrict__ E1,
    const float* __restrict__ E2, const float* __restrict__ E3)
{
    __shared__ float s[32][257];
    int stage = blockIdx.y;
    const float* E = (stage == 0) ? E0 : (stage == 1) ? E1 : (stage == 2) ? E2 : E3;
    int row0 = blockIdx.x * 32, tid = threadIdx.x;
#pragma unroll
    for (int i = 0; i < 32; i++) {
        int idx = tid + i * 256, r = idx >> 8, c = idx & 255;
        s[r][c] = E[(size_t)(row0 + r) * CDIM + c];
    }
    __syncthreads();
    if (tid < 32) {
        float acc = 0.f;
#pragma unroll 8
        for (int c = 0; c < CDIM; c++) {
            float v = s[tid][c];
            acc = __fadd_rn(acc, __fmul_rn(v, v));
        }
        g_esq[stage][row0 + tid] = acc;
    }
}

// ============================================================================
// ||ze||^2 (stage 0 only; later stages fused into gather)
// ============================================================================
__global__ __launch_bounds__(256) void rownorm_kernel(const float* __restrict__ ze)
{
    __shared__ float s[32][257];
    int row0 = blockIdx.x * 32, tid = threadIdx.x;
#pragma unroll
    for (int i = 0; i < 32; i++) {
        int idx = tid + i * 256, r = idx >> 8, c = idx & 255;
        s[r][c] = ze[(size_t)(row0 + r) * CDIM + c];
    }
    __syncthreads();
    if (tid < 32) {
        float acc = 0.f;
#pragma unroll 8
        for (int c = 0; c < CDIM; c++) {
            float v = s[tid][c];
            acc = __fadd_rn(acc, __fmul_rn(v, v));
        }
        g_ze2[row0 + tid] = acc;
    }
}

// ============================================================================
// PASS 1: fp16 screening, A split hi/lo (2 planes), B single fp16 plane.
// s~ = (ah+al)*bh; |s~-s| <= ||a||*2^-12*||b|| ~ 2e-3; BAND covers 2x bound.
// 256 thr (8 warps), 128 rows/CTA; 128 chunks of 32 codes; B bulk-copied
// (16KB/chunk, dbuf, mbarrier); ldmatrix fragment loads.
// ============================================================================
#define P1_ASTR 264
#define P1_BOFF 135168
#define P1_SMEM (135168 + 32768)

__global__ __launch_bounds__(256, 1) void vq_pass1_kernel(
    const float* __restrict__ ze, int stage)
{
    extern __shared__ char smc[];
    __half* Ah = (__half*)(smc);
    __half* Al = (__half*)(smc + 67584);
    __shared__ __align__(8) ull mbar[2];

    const int tid = threadIdx.x;
    const int w = tid >> 5, lane = tid & 31;
    const int g = lane >> 2, tig = lane & 3;
    const int row0 = blockIdx.x * 128;
    const float* __restrict__ esq = g_esq[stage];
    const __half* __restrict__ PB = g_PB[stage];
    const uint32_t sb = (uint32_t)__cvta_generic_to_shared(smc);
    const uint32_t mb0 = (uint32_t)__cvta_generic_to_shared(&mbar[0]);
    const uint32_t mb1 = (uint32_t)__cvta_generic_to_shared(&mbar[1]);

    if (tid == 0) { mbar_init(mb0); mbar_init(mb1); }
    __syncthreads();

    // prefetch chunk 0 into buffer 0 (16KB)
    if (tid == 0) {
        mbar_expect(mb0, 16384u);
        bulk_cp(sb + P1_BOFF, PB, 16384u, mb0);
    }

    // fill persistent A planes (split ze into fp16 hi+lo)
#pragma unroll 4
    for (int i = 0; i < 32; i++) {
        int idx = tid + i * 256;
        int r = idx >> 6, c4 = idx & 63;
        float4 f = *(const float4*)(ze + (size_t)(row0 + r) * CDIM + c4 * 4);
        __half2 h01, h23, l01, l23;
        h01.x = __float2half(f.x); l01.x = __float2half(f.x - __half2float(h01.x));
        h01.y = __float2half(f.y); l01.y = __float2half(f.y - __half2float(h01.y));
        h23.x = __float2half(f.z); l23.x = __float2half(f.z - __half2float(h23.x));
        h23.y = __float2half(f.w); l23.y = __float2half(f.w - __half2float(h23.y));
        int o = r * P1_ASTR + c4 * 4;
        *(__half2*)(Ah + o) = h01; *(__half2*)(Ah + o + 2) = h23;
        *(__half2*)(Al + o) = l01; *(__half2*)(Al + o + 2) = l23;
    }

    float m1[2] = {3.4e38f, 3.4e38f}, m2[2] = {3.4e38f, 3.4e38f};
    int   i1[2] = {0, 0};

    // ldmatrix lane pointers (same fragment conventions as round 13)
    const uint32_t a_off =
        (uint32_t)(((w * 16 + (lane & 15)) * P1_ASTR + ((lane >> 4) << 3)) * 2);
    const uint32_t ah_base = sb + a_off;
    const uint32_t al_base = sb + 67584u + a_off;
    const uint32_t brow512 = (uint32_t)((((lane >> 4) << 3) + (lane & 7)) * 512);
    const int kb = (lane >> 3) & 1;
    const int bx = lane & 7;

    for (int t = 0; t < 128; t++) {
        mbar_wait((t & 1) ? mb1 : mb0, (t >> 1) & 1);
        __syncthreads();

        if (t < 127 && tid == 0) {
            const uint32_t dst = sb + P1_BOFF + ((t + 1) & 1) * 16384u;
            const uint32_t mb = ((t + 1) & 1) ? mb1 : mb0;
            mbar_expect(mb, 16384u);
            bulk_cp(dst, PB + (size_t)(t + 1) * 8192, 16384u, mb);
        }

        const uint32_t Bp = sb + P1_BOFF + (uint32_t)((t & 1) * 16384);

        float acc[4][4];
#pragma unroll
        for (int nt = 0; nt < 4; nt++)
#pragma unroll
            for (int j = 0; j < 4; j++) acc[nt][j] = 0.f;

#pragma unroll 8
        for (int k = 0; k < 16; k++) {
            uint32_t ah[4], al[4];
            ldsm4(ah[0], ah[1], ah[2], ah[3], ah_base + (uint32_t)(k * 32));
            ldsm4(al[0], al[1], al[2], al[3], al_base + (uint32_t)(k * 32));

            const uint32_t blk = (uint32_t)((((k << 1) | kb) ^ bx) << 4);
            uint32_t b0[4], b1[4];
            ldsm4(b0[0], b0[1], b0[2], b0[3], Bp + brow512 + blk);
            ldsm4(b1[0], b1[1], b1[2], b1[3], Bp + 8192u + brow512 + blk);

            // ah*b
            mma16816h(acc[0], ah, b0[0], b0[1]);
            mma16816h(acc[1], ah, b0[2], b0[3]);
            mma16816h(acc[2], ah, b1[0], b1[1]);
            mma16816h(acc[3], ah, b1[2], b1[3]);
            // al*b
            mma16816h(acc[0], al, b0[0], b0[1]);
            mma16816h(acc[1], al, b0[2], b0[3]);
            mma16816h(acc[2], al, b1[0], b1[1]);
            mma16816h(acc[3], al, b1[2], b1[3]);
        }

        // epilogue: per-thread min1/min2 over this chunk's codes
        const int code0 = t * 32;
#pragma unroll
        for (int nt = 0; nt < 4; nt++) {
            int c0 = code0 + nt * 8 + 2 * tig;
            float e0 = esq[c0], e1 = esq[c0 + 1];
#pragma unroll
            for (int s = 0; s < 2; s++) {       // s=0: row g, s=1: row g+8
                float d0 = fmaf(-2.f, acc[nt][s * 2 + 0], e0);
                if (d0 < m1[s]) { m2[s] = m1[s]; m1[s] = d0; i1[s] = c0; }
                else if (d0 < m2[s]) m2[s] = d0;
                float d1 = fmaf(-2.f, acc[nt][s * 2 + 1], e1);
                if (d1 < m1[s]) { m2[s] = m1[s]; m1[s] = d1; i1[s] = c0 + 1; }
                else if (d1 < m2[s]) m2[s] = d1;
            }
        }
    }

    // merge across the 4 tig lanes sharing each row
#pragma unroll
    for (int s = 0; s < 2; s++) {
#pragma unroll
        for (int off = 1; off <= 2; off <<= 1) {
            float o1 = __shfl_xor_sync(0xffffffffu, m1[s], off);
            int   oi = __shfl_xor_sync(0xffffffffu, i1[s], off);
            float o2 = __shfl_xor_sync(0xffffffffu, m2[s], off);
            float nm2 = fminf(fmaxf(m1[s], o1), fminf(m2[s], o2));
            if (o1 < m1[s] || (o1 == m1[s] && oi < i1[s])) { m1[s] = o1; i1[s] = oi; }
            m2[s] = nm2;
        }
    }
    if (tig == 0) {
#pragma unroll
        for (int s = 0; s < 2; s++) {
            int row = row0 + w * 16 + g + s * 8;
            g_p1v1[row] = m1[s];
            g_p1v2[row] = m2[s];
            g_p1i1[row] = i1[s];
            g_fbkey[row] = ~0ull;
            if (m2[s] - m1[s] <= BAND) {
                int pos = atomicAdd(&g_fbcount[stage], 1);
                g_fbrows[pos] = row;
            }
        }
    }
}

// ============================================================================
// PASS 2: exact fallback (exact reference arithmetic + atomicMin on monotone
// key -> exact argmin, lowest-index ties).
// ============================================================================
#define FB_SMEM ((256 * 68 + 32 * 132) * 4 + 256)

__global__ __launch_bounds__(256) void vq_fallback_kernel(
    const float* __restrict__ ze, const float* __restrict__ E, int stage)
{
    extern __shared__ __align__(16) float fsm[];
    float* As = fsm;
    float* Bs = fsm + 256 * 68;
    int* rowsm = (int*)(fsm + 256 * 68 + 32 * 132);

    const int cnt = g_fbcount[stage];
    const int tid = threadIdx.x, tx = tid & 15, ty = tid >> 4;
    const int seg0 = blockIdx.y * 512;
    const float* __restrict__ esq = g_esq[stage];

    for (int base = blockIdx.x * 64; base < cnt; base += gridDim.x * 64) {
        __syncthreads();
        if (tid < 64) rowsm[tid] = (base + tid < cnt) ? g_fbrows[base + tid] : -1;
        __syncthreads();
#pragma unroll 4
        for (int i = 0; i < 64; i++) {
            int idx = tid + i * 256;
            int r = idx >> 8, c = idx & 255;
            int rr = rowsm[r];
            As[c * 68 + r] = (rr >= 0) ? ze[(size_t)rr * CDIM + c] : 0.f;
        }
        float zrow[4]; int rid[4];
#pragma unroll
        for (int i = 0; i < 4; i++) {
            rid[i] = rowsm[ty * 4 + i];
            zrow[i] = (rid[i] >= 0) ? g_ze2[rid[i]] : 0.f;
        }
        float bestv[4]; int besti[4];
#pragma unroll
        for (int i = 0; i < 4; i++) { bestv[i] = 3.4e38f; besti[i] = 0; }
        __syncthreads();

        for (int cb = 0; cb < 512; cb += 128) {
            ull acc[4][4];
#pragma unroll
            for (int i = 0; i < 4; i++)
#pragma unroll
                for (int j = 0; j < 4; j++) acc[i][j] = 0ull;

            for (int c0 = 0; c0 < CDIM; c0 += 32) {
#pragma unroll
                for (int i = 0; i < 16; i++) {
                    int idx = tid + i * 256;
                    int code = idx >> 5, kk = idx & 31;
                    Bs[kk * 132 + code] =
                        E[(size_t)(seg0 + cb + code) * CDIM + c0 + kk];
                }
                __syncthreads();
#pragma unroll
                for (int kk = 0; kk < 32; kk++) {
                    const float* ar = As + (c0 + kk) * 68;
                    const float* br = Bs + kk * 132;
                    float4 a0 = *(const float4*)&ar[ty * 4];
                    ull aa[4] = {dup2(a0.x), dup2(a0.y), dup2(a0.z), dup2(a0.w)};
                    ulonglong2 b0 = *(const ulonglong2*)&br[tx * 4];
                    ulonglong2 b1 = *(const ulonglong2*)&br[64 + tx * 4];
                    ull bb[4] = {b0.x, b0.y, b1.x, b1.y};
#pragma unroll
                    for (int i = 0; i < 4; i++)
#pragma unroll
                        for (int j = 0; j < 4; j++) fma2(acc[i][j], aa[i], bb[j]);
                }
                __syncthreads();
            }
#pragma unroll
            for (int jh = 0; jh < 2; jh++) {
#pragma unroll
                for (int h = 0; h < 2; h++) {
                    int j2 = jh * 2 + h;
                    int col = seg0 + cb + jh * 64 + tx * 4 + h * 2;
                    float eq0 = esq[col], eq1 = esq[col + 1];
#pragma unroll
                    for (int i = 0; i < 4; i++) {
                        float2 pv = unpk2(acc[i][j2]);
                        float v0 = __fadd_rn(__fadd_rn(zrow[i], -__fmul_rn(2.f, pv.x)), eq0);
                        if (v0 < bestv[i]) { bestv[i] = v0; besti[i] = col; }
                        float v1 = __fadd_rn(__fadd_rn(zrow[i], -__fmul_rn(2.f, pv.y)), eq1);
                        if (v1 < bestv[i]) { bestv[i] = v1; besti[i] = col + 1; }
                    }
                }
            }
        }

#pragma unroll
        for (int i = 0; i < 4; i++) {
            float v = bestv[i]; int ix = besti[i];
#pragma unroll
            for (int off = 1; off <= 8; off <<= 1) {
                float ov = __shfl_xor_sync(0xffffffffu, v, off);
                int   oi = __shfl_xor_sync(0xffffffffu, ix, off);
                if (ov < v || (ov == v && oi < ix)) { v = ov; ix = oi; }
            }
            if (tx == 0 && rid[i] >= 0)
                atomicMin(&g_fbkey[rid[i]], dkey(v, ix));
        }
    }
}

// ============================================================================
// Gather: resolve nn; zq; residual; zq_sum; stage-3 straight-through;
// next-stage ||ze||^2 fused.
// ============================================================================
__global__ void gather_kernel(const float* __restrict__ ze,
                              const float* __restrict__ E,
                              float* __restrict__ zq_out,
                              float* __restrict__ ze_next,
                              float* __restrict__ nn_f,
                              const float* __restrict__ ze1,
                              int stage)
{
    __shared__ float buf[CDIM];
    int row = blockIdx.x, c = threadIdx.x;
    int idx = (g_p1v2[row] - g_p1v1[row] <= BAND)
                  ? (int)(unsigned)(g_fbkey[row] & 0xffffffffull)
                  : g_p1i1[row];

    float q = E[(size_t)idx * CDIM + c];
    size_t o = (size_t)row * CDIM + c;
    zq_out[o] = q;
    if (ze_next) {
        float zn = __fadd_rn(ze[o], -q);
        ze_next[o] = zn;
        buf[c] = zn;
    }
    float s = (stage == 0) ? q : __fadd_rn(g_zqsum[o], q);
    if (stage == 3) {
        float z1 = ze1[o];
        s = __fadd_rn(z1, __fadd_rn(s, -z1));
    }
    g_zqsum[o] = s;
    if (c == 0) nn_f[row] = (float)idx;

    if (ze_next) {
        __syncthreads();
        if (c == 0) {
            float acc = 0.f;
#pragma unroll 8
            for (int i = 0; i < CDIM; i++)
                acc = __fadd_rn(acc, __fmul_rn(buf[i], buf[i]));
            g_ze2[row] = acc;
        }
    }
}

// ============================================================================
// kernel_launch — output: x_hat | ze_1..4 | zq_1..4 | nn_1..4
// ============================================================================
extern "C" void kernel_launch(void* const* d_in, const int* in_sizes, int n_in,
                              void* d_out, int out_size)
{
    const float* x     = (const float*)d_in[0];
    const float* W_enc = (const float*)d_in[1];
    const float* b_enc = (const float*)d_in[2];
    const float* E[4]  = {(const float*)d_in[3], (const float*)d_in[4],
                          (const float*)d_in[5], (const float*)d_in[6]};
    const float* W_dec = (const float*)d_in[7];
    const float* b_dec = (const float*)d_in[8];

    float* out = (float*)d_out;
    const size_t NC     = (size_t)NROWS * CDIM;
    const size_t OFF_ZE = (size_t)NROWS * INDIM;
    const size_t OFF_ZQ = OFF_ZE + 4 * NC;
    const size_t OFF_NN = OFF_ZQ + 4 * NC;
    const float* ze1 = out + OFF_ZE;

    void* zqsum_ptr = nullptr;
    cudaGetSymbolAddress(&zqsum_ptr, g_zqsum);

    cudaFuncSetAttribute(vq_pass1_kernel,
                         cudaFuncAttributeMaxDynamicSharedMemorySize, P1_SMEM);
    cudaFuncSetAttribute(vq_fallback_kernel,
                         cudaFuncAttributeMaxDynamicSharedMemorySize, FB_SMEM);

    // one-time preprocessing
    esq4_kernel<<<dim3(KCODES / 32, 4), 256>>>(E[0], E[1], E[2], E[3]);
    pack_kernel<<<(4 * KCODES * 128) / 256, 256>>>(E[0], E[1], E[2], E[3]);

    // encoder
    sgemm_bias_kernel<<<dim3(CDIM / 128, NROWS / 128), 256>>>(
        x, W_enc, b_enc, out + OFF_ZE, NROWS, INDIM, CDIM);
    rownorm_kernel<<<NROWS / 32, 256>>>(out + OFF_ZE);

    // 4 sequential VQ stages
    for (int s = 0; s < 4; s++) {
        const float* zes = out + OFF_ZE + (size_t)s * NC;
        vq_pass1_kernel<<<NROWS / 128, 256, P1_SMEM>>>(zes, s);
        vq_fallback_kernel<<<dim3(32, 8), 256, FB_SMEM>>>(zes, E[s], s);
        float* zenext = (s < 3) ? (out + OFF_ZE + (size_t)(s + 1) * NC) : nullptr;
        gather_kernel<<<NROWS, 256>>>(zes, E[s],
                                      out + OFF_ZQ + (size_t)s * NC,
                                      zenext,
                                      out + OFF_NN + (size_t)s * NROWS,
                                      ze1, s);
    }

    // decoder
    sgemm_bias_kernel<<<dim3(INDIM / 128, NROWS / 128), 256>>>(
        (const float*)zqsum_ptr, W_dec, b_dec, out, NROWS, CDIM, INDIM);
}

// round 16
// speedup vs baseline: 2.4346x; 1.0764x over previous
#include <cuda_runtime.h>
#include <cuda_fp16.h>
#include <cstddef>
#include <cstdint>

#define NROWS 16384
#define INDIM 768
#define CDIM  256
#define KCODES 4096
#define BAND  1.2e-2f

typedef unsigned long long ull;

// ---- device scratch ----
__device__ float g_zqsum[NROWS * CDIM];
__device__ float g_esq[4][KCODES];
__device__ float g_ze2[NROWS];
__device__ float g_p1v1[NROWS];
__device__ float g_p1v2[NROWS];
__device__ int   g_p1i1[NROWS];
__device__ ull   g_fbkey[NROWS];
__device__ int   g_fbcount[4];
__device__ int   g_fbrows[NROWS];
// codebook fp16 plane, TILE-SWIZZLED layout (16KB per 32-code tile; 64
// consecutive codes = 32KB contiguous -> one bulk copy per 64-code chunk):
//   tile = code>>5, row = code&31, word = c>>1
//   elem offset = tile*8192 + row*256 + ((word ^ ((row&7)<<2)) << 1) + (c&1)
__device__ __half g_PB[4][KCODES * CDIM];

// ---- helpers ----
__device__ __forceinline__ void fma2(ull& d, ull a, ull b)
{ asm("fma.rn.f32x2 %0, %1, %2, %0;" : "+l"(d) : "l"(a), "l"(b)); }
__device__ __forceinline__ ull dup2(float x)
{ ull r; asm("mov.b64 %0, {%1, %1};" : "=l"(r) : "f"(x)); return r; }
__device__ __forceinline__ float2 unpk2(ull v)
{ float2 r; asm("mov.b64 {%0, %1}, %2;" : "=f"(r.x), "=f"(r.y) : "l"(v)); return r; }
__device__ __forceinline__ void mma16816h(float* d, const uint32_t* a,
                                          uint32_t b0, uint32_t b1)
{
    asm volatile(
        "mma.sync.aligned.m16n8k16.row.col.f32.f16.f16.f32 "
        "{%0,%1,%2,%3}, {%4,%5,%6,%7}, {%8,%9}, {%0,%1,%2,%3};"
        : "+f"(d[0]), "+f"(d[1]), "+f"(d[2]), "+f"(d[3])
        : "r"(a[0]), "r"(a[1]), "r"(a[2]), "r"(a[3]), "r"(b0), "r"(b1));
}
__device__ __forceinline__ void ldsm4(uint32_t& r0, uint32_t& r1,
                                      uint32_t& r2, uint32_t& r3, uint32_t a)
{
    asm volatile("ldmatrix.sync.aligned.m8n8.x4.shared.b16 {%0,%1,%2,%3}, [%4];"
                 : "=r"(r0), "=r"(r1), "=r"(r2), "=r"(r3) : "r"(a));
}
__device__ __forceinline__ ull dkey(float d, int code)
{
    uint32_t u = __float_as_uint(d);
    u = (u >> 31) ? ~u : (u | 0x80000000u);
    return ((ull)u << 32) | (unsigned)code;
}
__device__ __forceinline__ void mbar_init(uint32_t a)
{ asm volatile("mbarrier.init.shared.b64 [%0], 1;" :: "r"(a) : "memory"); }
__device__ __forceinline__ void mbar_expect(uint32_t a, uint32_t bytes)
{ asm volatile("mbarrier.arrive.expect_tx.shared.b64 _, [%0], %1;" :: "r"(a), "r"(bytes) : "memory"); }
__device__ __forceinline__ void mbar_wait(uint32_t a, int phase)
{
    asm volatile(
        "{\n\t.reg .pred p;\n"
        "L%=:\n\t"
        "mbarrier.try_wait.parity.acquire.cta.shared::cta.b64 p, [%0], %1;\n\t"
        "@!p bra L%=;\n\t}"
        :: "r"(a), "r"(phase) : "memory");
}
__device__ __forceinline__ void bulk_cp(uint32_t dst, const void* src,
                                        uint32_t bytes, uint32_t mbar)
{
    asm volatile(
        "cp.async.bulk.shared::cta.global.mbarrier::complete_tx::bytes "
        "[%0], [%1], %2, [%3];"
        :: "r"(dst), "l"(src), "r"(bytes), "r"(mbar) : "memory");
}

// ============================================================================
// exact fp32 SGEMM + bias via packed f32x2 (bit-matches reference)
// ============================================================================
__global__ __launch_bounds__(256) void sgemm_bias_kernel(
    const float* __restrict__ A, const float* __restrict__ B,
    const float* __restrict__ bias, float* __restrict__ C,
    int M, int Kd, int Nn)
{
    __shared__ __align__(16) float As[32][132];
    __shared__ __align__(16) float Bs[32][132];
    const int tid = threadIdx.x, tx = tid & 15, ty = tid >> 4;
    const int m0 = blockIdx.y * 128, n0 = blockIdx.x * 128;

    ull acc[8][4];
#pragma unroll
    for (int i = 0; i < 8; i++)
#pragma unroll
        for (int j = 0; j < 4; j++) acc[i][j] = 0ull;

    for (int k0 = 0; k0 < Kd; k0 += 32) {
#pragma unroll
        for (int i = 0; i < 16; i++) {
            int idx = tid + i * 256, mm = idx >> 5, kk = idx & 31;
            As[kk][mm] = A[(size_t)(m0 + mm) * Kd + (k0 + kk)];
        }
#pragma unroll
        for (int i = 0; i < 16; i++) {
            int idx = tid + i * 256, kk = idx >> 7, nn = idx & 127;
            Bs[kk][nn] = B[(size_t)(k0 + kk) * Nn + (n0 + nn)];
        }
        __syncthreads();
#pragma unroll
        for (int kk = 0; kk < 32; kk++) {
            float4 a0 = *(const float4*)&As[kk][ty * 4];
            float4 a1 = *(const float4*)&As[kk][64 + ty * 4];
            ull aa[8] = {dup2(a0.x), dup2(a0.y), dup2(a0.z), dup2(a0.w),
                         dup2(a1.x), dup2(a1.y), dup2(a1.z), dup2(a1.w)};
            ulonglong2 b0 = *(const ulonglong2*)&Bs[kk][tx * 4];
            ulonglong2 b1 = *(const ulonglong2*)&Bs[kk][64 + tx * 4];
            ull bb[4] = {b0.x, b0.y, b1.x, b1.y};
#pragma unroll
            for (int i = 0; i < 8; i++)
#pragma unroll
                for (int j = 0; j < 4; j++) fma2(acc[i][j], aa[i], bb[j]);
        }
        __syncthreads();
    }
#pragma unroll
    for (int i = 0; i < 8; i++) {
        int row = m0 + ((i < 4) ? (ty * 4 + i) : (64 + ty * 4 + (i - 4)));
#pragma unroll
        for (int jh = 0; jh < 2; jh++) {
            int col = n0 + (jh ? (64 + tx * 4) : (tx * 4));
            float2 p0 = unpk2(acc[i][jh * 2 + 0]);
            float2 p1 = unpk2(acc[i][jh * 2 + 1]);
            float4 v;
            v.x = __fadd_rn(p0.x, bias[col + 0]);
            v.y = __fadd_rn(p0.y, bias[col + 1]);
            v.z = __fadd_rn(p1.x, bias[col + 2]);
            v.w = __fadd_rn(p1.y, bias[col + 3]);
            *(float4*)&C[(size_t)row * Nn + col] = v;
        }
    }
}

// ============================================================================
// pack codebooks into tile-swizzled fp16 plane + zero fb counters
// ============================================================================
__global__ void pack_kernel(const float* __restrict__ E0,
                            const float* __restrict__ E1,
                            const float* __restrict__ E2,
                            const float* __restrict__ E3)
{
    int gid = blockIdx.x * 256 + threadIdx.x;
    if (gid < 4) g_fbcount[gid] = 0;
    int stage = gid >> 19;
    int rem = gid & 524287;
    int code = rem >> 7, word = rem & 127;
    const float* E = (stage == 0) ? E0 : (stage == 1) ? E1 : (stage == 2) ? E2 : E3;
    float f0 = E[(size_t)code * CDIM + word * 2];
    float f1 = E[(size_t)code * CDIM + word * 2 + 1];
    int tile = code >> 5, row = code & 31;
    int off = tile * 8192 + row * 256 + ((word ^ ((row & 7) << 2)) << 1);
    g_PB[stage][off] = __float2half(f0);
    g_PB[stage][off + 1] = __float2half(f1);
}

// ============================================================================
// ||E_k||^2 (exact sequential XLA chain), coalesced via smem staging
// ============================================================================
__global__ __launch_bounds__(256) void esq4_kernel(
    const float* __restrict__ E0, const float* __restrict__ E1,
    const float* __restrict__ E2, const float* __restrict__ E3)
{
    __shared__ float s[32][257];
    int stage = blockIdx.y;
    const float* E = (stage == 0) ? E0 : (stage == 1) ? E1 : (stage == 2) ? E2 : E3;
    int row0 = blockIdx.x * 32, tid = threadIdx.x;
#pragma unroll
    for (int i = 0; i < 32; i++) {
        int idx = tid + i * 256, r = idx >> 8, c = idx & 255;
        s[r][c] = E[(size_t)(row0 + r) * CDIM + c];
    }
    __syncthreads();
    if (tid < 32) {
        float acc = 0.f;
#pragma unroll 8
        for (int c = 0; c < CDIM; c++) {
            float v = s[tid][c];
            acc = __fadd_rn(acc, __fmul_rn(v, v));
        }
        g_esq[stage][row0 + tid] = acc;
    }
}

// ============================================================================
// ||ze||^2 (stage 0 only; later stages fused into gather)
// ============================================================================
__global__ __launch_bounds__(256) void rownorm_kernel(const float* __restrict__ ze)
{
    __shared__ float s[32][257];
    int row0 = blockIdx.x * 32, tid = threadIdx.x;
#pragma unroll
    for (int i = 0; i < 32; i++) {
        int idx = tid + i * 256, r = idx >> 8, c = idx & 255;
        s[r][c] = ze[(size_t)(row0 + r) * CDIM + c];
    }
    __syncthreads();
    if (tid < 32) {
        float acc = 0.f;
#pragma unroll 8
        for (int c = 0; c < CDIM; c++) {
            float v = s[tid][c];
            acc = __fadd_rn(acc, __fmul_rn(v, v));
        }
        g_ze2[row0 + tid] = acc;
    }
}

// ============================================================================
// PASS 1: fp16 screening, A split hi/lo (2 planes), B single fp16 plane.
// 64-CODE CHUNKS (vs 32): 1.5 crossbar-wavefronts per HMMA (vs 2.0), half
// the chunk boundaries. s~ = (ah+al)*bh; BAND covers 2x the drop bound.
// 256 thr (8 warps), 128 rows/CTA; 64 chunks; B bulk-copied 32KB/chunk
// (dbuf, mbarrier); ldmatrix fragment loads.
// ============================================================================
#define P1_ASTR 264
#define P1_BOFF 135168
#define P1_SMEM (135168 + 65536)

__global__ __launch_bounds__(256, 1) void vq_pass1_kernel(
    const float* __restrict__ ze, int stage)
{
    extern __shared__ char smc[];
    __half* Ah = (__half*)(smc);
    __half* Al = (__half*)(smc + 67584);
    __shared__ __align__(8) ull mbar[2];

    const int tid = threadIdx.x;
    const int w = tid >> 5, lane = tid & 31;
    const int g = lane >> 2, tig = lane & 3;
    const int row0 = blockIdx.x * 128;
    const float* __restrict__ esq = g_esq[stage];
    const __half* __restrict__ PB = g_PB[stage];
    const uint32_t sb = (uint32_t)__cvta_generic_to_shared(smc);
    const uint32_t mb0 = (uint32_t)__cvta_generic_to_shared(&mbar[0]);
    const uint32_t mb1 = (uint32_t)__cvta_generic_to_shared(&mbar[1]);

    if (tid == 0) { mbar_init(mb0); mbar_init(mb1); }
    __syncthreads();

    // prefetch chunk 0 into buffer 0 (32KB = 64 codes)
    if (tid == 0) {
        mbar_expect(mb0, 32768u);
        bulk_cp(sb + P1_BOFF, PB, 32768u, mb0);
    }

    // fill persistent A planes (split ze into fp16 hi+lo)
#pragma unroll 4
    for (int i = 0; i < 32; i++) {
        int idx = tid + i * 256;
        int r = idx >> 6, c4 = idx & 63;
        float4 f = *(const float4*)(ze + (size_t)(row0 + r) * CDIM + c4 * 4);
        __half2 h01, h23, l01, l23;
        h01.x = __float2half(f.x); l01.x = __float2half(f.x - __half2float(h01.x));
        h01.y = __float2half(f.y); l01.y = __float2half(f.y - __half2float(h01.y));
        h23.x = __float2half(f.z); l23.x = __float2half(f.z - __half2float(h23.x));
        h23.y = __float2half(f.w); l23.y = __float2half(f.w - __half2float(h23.y));
        int o = r * P1_ASTR + c4 * 4;
        *(__half2*)(Ah + o) = h01; *(__half2*)(Ah + o + 2) = h23;
        *(__half2*)(Al + o) = l01; *(__half2*)(Al + o + 2) = l23;
    }

    float m1[2] = {3.4e38f, 3.4e38f}, m2[2] = {3.4e38f, 3.4e38f};
    int   i1[2] = {0, 0};

    // ldmatrix lane pointers (same fragment conventions as before)
    const uint32_t a_off =
        (uint32_t)(((w * 16 + (lane & 15)) * P1_ASTR + ((lane >> 4) << 3)) * 2);
    const uint32_t ah_base = sb + a_off;
    const uint32_t al_base = sb + 67584u + a_off;
    const uint32_t brow512 = (uint32_t)((((lane >> 4) << 3) + (lane & 7)) * 512);
    const int kb = (lane >> 3) & 1;
    const int bx = lane & 7;

    for (int t = 0; t < 64; t++) {
        mbar_wait((t & 1) ? mb1 : mb0, (t >> 1) & 1);
        __syncthreads();

        if (t < 63 && tid == 0) {
            const uint32_t dst = sb + P1_BOFF + ((t + 1) & 1) * 32768u;
            const uint32_t mb = ((t + 1) & 1) ? mb1 : mb0;
            mbar_expect(mb, 32768u);
            bulk_cp(dst, PB + (size_t)(t + 1) * 16384, 32768u, mb);
        }

        const uint32_t Bp = sb + P1_BOFF + (uint32_t)((t & 1) * 32768);

        float acc[8][4];
#pragma unroll
        for (int nt = 0; nt < 8; nt++)
#pragma unroll
            for (int j = 0; j < 4; j++) acc[nt][j] = 0.f;

#pragma unroll 4
        for (int k = 0; k < 16; k++) {
            uint32_t ah[4], al[4];
            ldsm4(ah[0], ah[1], ah[2], ah[3], ah_base + (uint32_t)(k * 32));
            ldsm4(al[0], al[1], al[2], al[3], al_base + (uint32_t)(k * 32));

            const uint32_t blk = (uint32_t)((((k << 1) | kb) ^ bx) << 4);
            uint32_t b0[4], b1[4], b2[4], b3[4];
            ldsm4(b0[0], b0[1], b0[2], b0[3], Bp + brow512 + blk);
            ldsm4(b1[0], b1[1], b1[2], b1[3], Bp + 8192u + brow512 + blk);
            ldsm4(b2[0], b2[1], b2[2], b2[3], Bp + 16384u + brow512 + blk);
            ldsm4(b3[0], b3[1], b3[2], b3[3], Bp + 24576u + brow512 + blk);

            // ah * b (codes 0..63)
            mma16816h(acc[0], ah, b0[0], b0[1]);
            mma16816h(acc[1], ah, b0[2], b0[3]);
            mma16816h(acc[2], ah, b1[0], b1[1]);
            mma16816h(acc[3], ah, b1[2], b1[3]);
            mma16816h(acc[4], ah, b2[0], b2[1]);
            mma16816h(acc[5], ah, b2[2], b2[3]);
            mma16816h(acc[6], ah, b3[0], b3[1]);
            mma16816h(acc[7], ah, b3[2], b3[3]);
            // al * b
            mma16816h(acc[0], al, b0[0], b0[1]);
            mma16816h(acc[1], al, b0[2], b0[3]);
            mma16816h(acc[2], al, b1[0], b1[1]);
            mma16816h(acc[3], al, b1[2], b1[3]);
            mma16816h(acc[4], al, b2[0], b2[1]);
            mma16816h(acc[5], al, b2[2], b2[3]);
            mma16816h(acc[6], al, b3[0], b3[1]);
            mma16816h(acc[7], al, b3[2], b3[3]);
        }

        // epilogue: per-thread min1/min2 over this chunk's 64 codes
        const int code0 = t * 64;
#pragma unroll
        for (int nt = 0; nt < 8; nt++) {
            int c0 = code0 + nt * 8 + 2 * tig;
            float e0 = esq[c0], e1 = esq[c0 + 1];
#pragma unroll
            for (int s = 0; s < 2; s++) {       // s=0: row g, s=1: row g+8
                float d0 = fmaf(-2.f, acc[nt][s * 2 + 0], e0);
                if (d0 < m1[s]) { m2[s] = m1[s]; m1[s] = d0; i1[s] = c0; }
                else if (d0 < m2[s]) m2[s] = d0;
                float d1 = fmaf(-2.f, acc[nt][s * 2 + 1], e1);
                if (d1 < m1[s]) { m2[s] = m1[s]; m1[s] = d1; i1[s] = c0 + 1; }
                else if (d1 < m2[s]) m2[s] = d1;
            }
        }
    }

    // merge across the 4 tig lanes sharing each row
#pragma unroll
    for (int s = 0; s < 2; s++) {
#pragma unroll
        for (int off = 1; off <= 2; off <<= 1) {
            float o1 = __shfl_xor_sync(0xffffffffu, m1[s], off);
            int   oi = __shfl_xor_sync(0xffffffffu, i1[s], off);
            float o2 = __shfl_xor_sync(0xffffffffu, m2[s], off);
            float nm2 = fminf(fmaxf(m1[s], o1), fminf(m2[s], o2));
            if (o1 < m1[s] || (o1 == m1[s] && oi < i1[s])) { m1[s] = o1; i1[s] = oi; }
            m2[s] = nm2;
        }
    }
    if (tig == 0) {
#pragma unroll
        for (int s = 0; s < 2; s++) {
            int row = row0 + w * 16 + g + s * 8;
            g_p1v1[row] = m1[s];
            g_p1v2[row] = m2[s];
            g_p1i1[row] = i1[s];
            g_fbkey[row] = ~0ull;
            if (m2[s] - m1[s] <= BAND) {
                int pos = atomicAdd(&g_fbcount[stage], 1);
                g_fbrows[pos] = row;
            }
        }
    }
}

// ============================================================================
// PASS 2: exact fallback (exact reference arithmetic + atomicMin on monotone
// key -> exact argmin, lowest-index ties).
// ============================================================================
#define FB_SMEM ((256 * 68 + 32 * 132) * 4 + 256)

__global__ __launch_bounds__(256) void vq_fallback_kernel(
    const float* __restrict__ ze, const float* __restrict__ E, int stage)
{
    extern __shared__ __align__(16) float fsm[];
    float* As = fsm;
    float* Bs = fsm + 256 * 68;
    int* rowsm = (int*)(fsm + 256 * 68 + 32 * 132);

    const int cnt = g_fbcount[stage];
    const int tid = threadIdx.x, tx = tid & 15, ty = tid >> 4;
    const int seg0 = blockIdx.y * 512;
    const float* __restrict__ esq = g_esq[stage];

    for (int base = blockIdx.x * 64; base < cnt; base += gridDim.x * 64) {
        __syncthreads();
        if (tid < 64) rowsm[tid] = (base + tid < cnt) ? g_fbrows[base + tid] : -1;
        __syncthreads();
#pragma unroll 4
        for (int i = 0; i < 64; i++) {
            int idx = tid + i * 256;
            int r = idx >> 8, c = idx & 255;
            int rr = rowsm[r];
            As[c * 68 + r] = (rr >= 0) ? ze[(size_t)rr * CDIM + c] : 0.f;
        }
        float zrow[4]; int rid[4];
#pragma unroll
        for (int i = 0; i < 4; i++) {
            rid[i] = rowsm[ty * 4 + i];
            zrow[i] = (rid[i] >= 0) ? g_ze2[rid[i]] : 0.f;
        }
        float bestv[4]; int besti[4];
#pragma unroll
        for (int i = 0; i < 4; i++) { bestv[i] = 3.4e38f; besti[i] = 0; }
        __syncthreads();

        for (int cb = 0; cb < 512; cb += 128) {
            ull acc[4][4];
#pragma unroll
            for (int i = 0; i < 4; i++)
#pragma unroll
                for (int j = 0; j < 4; j++) acc[i][j] = 0ull;

            for (int c0 = 0; c0 < CDIM; c0 += 32) {
#pragma unroll
                for (int i = 0; i < 16; i++) {
                    int idx = tid + i * 256;
                    int code = idx >> 5, kk = idx & 31;
                    Bs[kk * 132 + code] =
                        E[(size_t)(seg0 + cb + code) * CDIM + c0 + kk];
                }
                __syncthreads();
#pragma unroll
                for (int kk = 0; kk < 32; kk++) {
                    const float* ar = As + (c0 + kk) * 68;
                    const float* br = Bs + kk * 132;
                    float4 a0 = *(const float4*)&ar[ty * 4];
                    ull aa[4] = {dup2(a0.x), dup2(a0.y), dup2(a0.z), dup2(a0.w)};
                    ulonglong2 b0 = *(const ulonglong2*)&br[tx * 4];
                    ulonglong2 b1 = *(const ulonglong2*)&br[64 + tx * 4];
                    ull bb[4] = {b0.x, b0.y, b1.x, b1.y};
#pragma unroll
                    for (int i = 0; i < 4; i++)
#pragma unroll
                        for (int j = 0; j < 4; j++) fma2(acc[i][j], aa[i], bb[j]);
                }
                __syncthreads();
            }
#pragma unroll
            for (int jh = 0; jh < 2; jh++) {
#pragma unroll
                for (int h = 0; h < 2; h++) {
                    int j2 = jh * 2 + h;
                    int col = seg0 + cb + jh * 64 + tx * 4 + h * 2;
                    float eq0 = esq[col], eq1 = esq[col + 1];
#pragma unroll
                    for (int i = 0; i < 4; i++) {
                        float2 pv = unpk2(acc[i][j2]);
                        float v0 = __fadd_rn(__fadd_rn(zrow[i], -__fmul_rn(2.f, pv.x)), eq0);
                        if (v0 < bestv[i]) { bestv[i] = v0; besti[i] = col; }
                        float v1 = __fadd_rn(__fadd_rn(zrow[i], -__fmul_rn(2.f, pv.y)), eq1);
                        if (v1 < bestv[i]) { bestv[i] = v1; besti[i] = col + 1; }
                    }
                }
            }
        }

#pragma unroll
        for (int i = 0; i < 4; i++) {
            float v = bestv[i]; int ix = besti[i];
#pragma unroll
            for (int off = 1; off <= 8; off <<= 1) {
                float ov = __shfl_xor_sync(0xffffffffu, v, off);
                int   oi = __shfl_xor_sync(0xffffffffu, ix, off);
                if (ov < v || (ov == v && oi < ix)) { v = ov; ix = oi; }
            }
            if (tx == 0 && rid[i] >= 0)
                atomicMin(&g_fbkey[rid[i]], dkey(v, ix));
        }
    }
}

// ============================================================================
// Gather: resolve nn; zq; residual; zq_sum; stage-3 straight-through;
// next-stage ||ze||^2 fused.
// ============================================================================
__global__ void gather_kernel(const float* __restrict__ ze,
                              const float* __restrict__ E,
                              float* __restrict__ zq_out,
                              float* __restrict__ ze_next,
                              float* __restrict__ nn_f,
                              const float* __restrict__ ze1,
                              int stage)
{
    __shared__ float buf[CDIM];
    int row = blockIdx.x, c = threadIdx.x;
    int idx = (g_p1v2[row] - g_p1v1[row] <= BAND)
                  ? (int)(unsigned)(g_fbkey[row] & 0xffffffffull)
                  : g_p1i1[row];

    float q = E[(size_t)idx * CDIM + c];
    size_t o = (size_t)row * CDIM + c;
    zq_out[o] = q;
    if (ze_next) {
        float zn = __fadd_rn(ze[o], -q);
        ze_next[o] = zn;
        buf[c] = zn;
    }
    float s = (stage == 0) ? q : __fadd_rn(g_zqsum[o], q);
    if (stage == 3) {
        float z1 = ze1[o];
        s = __fadd_rn(z1, __fadd_rn(s, -z1));
    }
    g_zqsum[o] = s;
    if (c == 0) nn_f[row] = (float)idx;

    if (ze_next) {
        __syncthreads();
        if (c == 0) {
            float acc = 0.f;
#pragma unroll 8
            for (int i = 0; i < CDIM; i++)
                acc = __fadd_rn(acc, __fmul_rn(buf[i], buf[i]));
            g_ze2[row] = acc;
        }
    }
}

// ============================================================================
// kernel_launch — output: x_hat | ze_1..4 | zq_1..4 | nn_1..4
// ============================================================================
extern "C" void kernel_launch(void* const* d_in, const int* in_sizes, int n_in,
                              void* d_out, int out_size)
{
    const float* x     = (const float*)d_in[0];
    const float* W_enc = (const float*)d_in[1];
    const float* b_enc = (const float*)d_in[2];
    const float* E[4]  = {(const float*)d_in[3], (const float*)d_in[4],
                          (const float*)d_in[5], (const float*)d_in[6]};
    const float* W_dec = (const float*)d_in[7];
    const float* b_dec = (const float*)d_in[8];

    float* out = (float*)d_out;
    const size_t NC     = (size_t)NROWS * CDIM;
    const size_t OFF_ZE = (size_t)NROWS * INDIM;
    const size_t OFF_ZQ = OFF_ZE + 4 * NC;
    const size_t OFF_NN = OFF_ZQ + 4 * NC;
    const float* ze1 = out + OFF_ZE;

    void* zqsum_ptr = nullptr;
    cudaGetSymbolAddress(&zqsum_ptr, g_zqsum);

    cudaFuncSetAttribute(vq_pass1_kernel,
                         cudaFuncAttributeMaxDynamicSharedMemorySize, P1_SMEM);
    cudaFuncSetAttribute(vq_fallback_kernel,
                         cudaFuncAttributeMaxDynamicSharedMemorySize, FB_SMEM);

    // one-time preprocessing
    esq4_kernel<<<dim3(KCODES / 32, 4), 256>>>(E[0], E[1], E[2], E[3]);
    pack_kernel<<<(4 * KCODES * 128) / 256, 256>>>(E[0], E[1], E[2], E[3]);

    // encoder
    sgemm_bias_kernel<<<dim3(CDIM / 128, NROWS / 128), 256>>>(
        x, W_enc, b_enc, out + OFF_ZE, NROWS, INDIM, CDIM);
    rownorm_kernel<<<NROWS / 32, 256>>>(out + OFF_ZE);

    // 4 sequential VQ stages
    for (int s = 0; s < 4; s++) {
        const float* zes = out + OFF_ZE + (size_t)s * NC;
        vq_pass1_kernel<<<NROWS / 128, 256, P1_SMEM>>>(zes, s);
        vq_fallback_kernel<<<dim3(32, 8), 256, FB_SMEM>>>(zes, E[s], s);
        float* zenext = (s < 3) ? (out + OFF_ZE + (size_t)(s + 1) * NC) : nullptr;
        gather_kernel<<<NROWS, 256>>>(zes, E[s],
                                      out + OFF_ZQ + (size_t)s * NC,
                                      zenext,
                                      out + OFF_NN + (size_t)s * NROWS,
                                      ze1, s);
    }

    // decoder
    sgemm_bias_kernel<<<dim3(INDIM / 128, NROWS / 128), 256>>>(
        (const float*)zqsum_ptr, W_dec, b_dec, out, NROWS, CDIM, INDIM);
}

// round 17
// speedup vs baseline: 2.5394x; 1.0430x over previous
#include <cuda_runtime.h>
#include <cuda_fp16.h>
#include <cstddef>
#include <cstdint>

#define NROWS 16384
#define INDIM 768
#define CDIM  256
#define KCODES 4096
#define BAND  1.2e-2f

typedef unsigned long long ull;

// ---- device scratch ----
__device__ float g_zqsum[NROWS * CDIM];
__device__ float g_esq[4][KCODES];
__device__ float g_ze2[NROWS];
__device__ float g_p1v1[NROWS];
__device__ float g_p1v2[NROWS];
__device__ int   g_p1i1[NROWS];
__device__ ull   g_fbkey[NROWS];
__device__ int   g_fbcount[4];
__device__ int   g_fbrows[NROWS];
// codebook fp16 plane, TILE-SWIZZLED layout (16KB per 32-code tile; 64
// consecutive codes = 32KB contiguous -> one bulk copy per 64-code chunk):
//   tile = code>>5, row = code&31, word = c>>1
//   elem offset = tile*8192 + row*256 + ((word ^ ((row&7)<<2)) << 1) + (c&1)
__device__ __half g_PB[4][KCODES * CDIM];

// ---- helpers ----
__device__ __forceinline__ void fma2(ull& d, ull a, ull b)
{ asm("fma.rn.f32x2 %0, %1, %2, %0;" : "+l"(d) : "l"(a), "l"(b)); }
__device__ __forceinline__ ull dup2(float x)
{ ull r; asm("mov.b64 %0, {%1, %1};" : "=l"(r) : "f"(x)); return r; }
__device__ __forceinline__ float2 unpk2(ull v)
{ float2 r; asm("mov.b64 {%0, %1}, %2;" : "=f"(r.x), "=f"(r.y) : "l"(v)); return r; }
__device__ __forceinline__ void mma16816h(float* d, const uint32_t* a,
                                          uint32_t b0, uint32_t b1)
{
    asm volatile(
        "mma.sync.aligned.m16n8k16.row.col.f32.f16.f16.f32 "
        "{%0,%1,%2,%3}, {%4,%5,%6,%7}, {%8,%9}, {%0,%1,%2,%3};"
        : "+f"(d[0]), "+f"(d[1]), "+f"(d[2]), "+f"(d[3])
        : "r"(a[0]), "r"(a[1]), "r"(a[2]), "r"(a[3]), "r"(b0), "r"(b1));
}
__device__ __forceinline__ void ldsm4(uint32_t& r0, uint32_t& r1,
                                      uint32_t& r2, uint32_t& r3, uint32_t a)
{
    asm volatile("ldmatrix.sync.aligned.m8n8.x4.shared.b16 {%0,%1,%2,%3}, [%4];"
                 : "=r"(r0), "=r"(r1), "=r"(r2), "=r"(r3) : "r"(a));
}
__device__ __forceinline__ ull dkey(float d, int code)
{
    uint32_t u = __float_as_uint(d);
    u = (u >> 31) ? ~u : (u | 0x80000000u);
    return ((ull)u << 32) | (unsigned)code;
}
__device__ __forceinline__ void mbar_init(uint32_t a)
{ asm volatile("mbarrier.init.shared.b64 [%0], 1;" :: "r"(a) : "memory"); }
__device__ __forceinline__ void mbar_expect(uint32_t a, uint32_t bytes)
{ asm volatile("mbarrier.arrive.expect_tx.shared.b64 _, [%0], %1;" :: "r"(a), "r"(bytes) : "memory"); }
__device__ __forceinline__ void mbar_wait(uint32_t a, int phase)
{
    asm volatile(
        "{\n\t.reg .pred p;\n"
        "L%=:\n\t"
        "mbarrier.try_wait.parity.acquire.cta.shared::cta.b64 p, [%0], %1;\n\t"
        "@!p bra L%=;\n\t}"
        :: "r"(a), "r"(phase) : "memory");
}
__device__ __forceinline__ void bulk_cp(uint32_t dst, const void* src,
                                        uint32_t bytes, uint32_t mbar)
{
    asm volatile(
        "cp.async.bulk.shared::cta.global.mbarrier::complete_tx::bytes "
        "[%0], [%1], %2, [%3];"
        :: "r"(dst), "l"(src), "r"(bytes), "r"(mbar) : "memory");
}

// ============================================================================
// exact fp32 SGEMM + bias via packed f32x2 (bit-matches reference)
// ============================================================================
__global__ __launch_bounds__(256) void sgemm_bias_kernel(
    const float* __restrict__ A, const float* __restrict__ B,
    const float* __restrict__ bias, float* __restrict__ C,
    int M, int Kd, int Nn)
{
    __shared__ __align__(16) float As[32][132];
    __shared__ __align__(16) float Bs[32][132];
    const int tid = threadIdx.x, tx = tid & 15, ty = tid >> 4;
    const int m0 = blockIdx.y * 128, n0 = blockIdx.x * 128;

    ull acc[8][4];
#pragma unroll
    for (int i = 0; i < 8; i++)
#pragma unroll
        for (int j = 0; j < 4; j++) acc[i][j] = 0ull;

    for (int k0 = 0; k0 < Kd; k0 += 32) {
#pragma unroll
        for (int i = 0; i < 16; i++) {
            int idx = tid + i * 256, mm = idx >> 5, kk = idx & 31;
            As[kk][mm] = A[(size_t)(m0 + mm) * Kd + (k0 + kk)];
        }
#pragma unroll
        for (int i = 0; i < 16; i++) {
            int idx = tid + i * 256, kk = idx >> 7, nn = idx & 127;
            Bs[kk][nn] = B[(size_t)(k0 + kk) * Nn + (n0 + nn)];
        }
        __syncthreads();
#pragma unroll
        for (int kk = 0; kk < 32; kk++) {
            float4 a0 = *(const float4*)&As[kk][ty * 4];
            float4 a1 = *(const float4*)&As[kk][64 + ty * 4];
            ull aa[8] = {dup2(a0.x), dup2(a0.y), dup2(a0.z), dup2(a0.w),
                         dup2(a1.x), dup2(a1.y), dup2(a1.z), dup2(a1.w)};
            ulonglong2 b0 = *(const ulonglong2*)&Bs[kk][tx * 4];
            ulonglong2 b1 = *(const ulonglong2*)&Bs[kk][64 + tx * 4];
            ull bb[4] = {b0.x, b0.y, b1.x, b1.y};
#pragma unroll
            for (int i = 0; i < 8; i++)
#pragma unroll
                for (int j = 0; j < 4; j++) fma2(acc[i][j], aa[i], bb[j]);
        }
        __syncthreads();
    }
#pragma unroll
    for (int i = 0; i < 8; i++) {
        int row = m0 + ((i < 4) ? (ty * 4 + i) : (64 + ty * 4 + (i - 4)));
#pragma unroll
        for (int jh = 0; jh < 2; jh++) {
            int col = n0 + (jh ? (64 + tx * 4) : (tx * 4));
            float2 p0 = unpk2(acc[i][jh * 2 + 0]);
            float2 p1 = unpk2(acc[i][jh * 2 + 1]);
            float4 v;
            v.x = __fadd_rn(p0.x, bias[col + 0]);
            v.y = __fadd_rn(p0.y, bias[col + 1]);
            v.z = __fadd_rn(p1.x, bias[col + 2]);
            v.w = __fadd_rn(p1.y, bias[col + 3]);
            *(float4*)&C[(size_t)row * Nn + col] = v;
        }
    }
}

// ============================================================================
// pack codebooks into tile-swizzled fp16 plane + zero fb counters
// ============================================================================
__global__ void pack_kernel(const float* __restrict__ E0,
                            const float* __restrict__ E1,
                            const float* __restrict__ E2,
                            const float* __restrict__ E3)
{
    int gid = blockIdx.x * 256 + threadIdx.x;
    if (gid < 4) g_fbcount[gid] = 0;
    int stage = gid >> 19;
    int rem = gid & 524287;
    int code = rem >> 7, word = rem & 127;
    const float* E = (stage == 0) ? E0 : (stage == 1) ? E1 : (stage == 2) ? E2 : E3;
    float f0 = E[(size_t)code * CDIM + word * 2];
    float f1 = E[(size_t)code * CDIM + word * 2 + 1];
    int tile = code >> 5, row = code & 31;
    int off = tile * 8192 + row * 256 + ((word ^ ((row & 7) << 2)) << 1);
    g_PB[stage][off] = __float2half(f0);
    g_PB[stage][off + 1] = __float2half(f1);
}

// ============================================================================
// ||E_k||^2 (exact sequential XLA chain), coalesced via smem staging
// ============================================================================
__global__ __launch_bounds__(256) void esq4_kernel(
    const float* __restrict__ E0, const float* __restrict__ E1,
    const float* __restrict__ E2, const float* __restrict__ E3)
{
    __shared__ float s[32][257];
    int stage = blockIdx.y;
    const float* E = (stage == 0) ? E0 : (stage == 1) ? E1 : (stage == 2) ? E2 : E3;
    int row0 = blockIdx.x * 32, tid = threadIdx.x;
#pragma unroll
    for (int i = 0; i < 32; i++) {
        int idx = tid + i * 256, r = idx >> 8, c = idx & 255;
        s[r][c] = E[(size_t)(row0 + r) * CDIM + c];
    }
    __syncthreads();
    if (tid < 32) {
        float acc = 0.f;
#pragma unroll 8
        for (int c = 0; c < CDIM; c++) {
            float v = s[tid][c];
            acc = __fadd_rn(acc, __fmul_rn(v, v));
        }
        g_esq[stage][row0 + tid] = acc;
    }
}

// ============================================================================
// ||ze||^2 (stage 0 only; later stages fused into gather)
// ============================================================================
__global__ __launch_bounds__(256) void rownorm_kernel(const float* __restrict__ ze)
{
    __shared__ float s[32][257];
    int row0 = blockIdx.x * 32, tid = threadIdx.x;
#pragma unroll
    for (int i = 0; i < 32; i++) {
        int idx = tid + i * 256, r = idx >> 8, c = idx & 255;
        s[r][c] = ze[(size_t)(row0 + r) * CDIM + c];
    }
    __syncthreads();
    if (tid < 32) {
        float acc = 0.f;
#pragma unroll 8
        for (int c = 0; c < CDIM; c++) {
            float v = s[tid][c];
            acc = __fadd_rn(acc, __fmul_rn(v, v));
        }
        g_ze2[row0 + tid] = acc;
    }
}

// ============================================================================
// PASS 1: fp16 screening, A split hi/lo, B single fp16 plane; 64-code chunks.
// 512 THREADS / 16 WARPS: warp w = (row-group w&7) x (code-half w>>3).
// Doubles warps/SMSP (2->4) to cover LDS/ldmatrix latency; per-row minima
// from the two code-halves are merged exactly at the end (disjoint ascending
// code ranges -> first-occurrence tie-break preserved).
// ============================================================================
#define P1_ASTR 264
#define P1_BOFF 135168
#define P1_SMEM (135168 + 65536)

__global__ __launch_bounds__(512, 1) void vq_pass1_kernel(
    const float* __restrict__ ze, int stage)
{
    extern __shared__ char smc[];
    __half* Ah = (__half*)(smc);
    __half* Al = (__half*)(smc + 67584);
    __shared__ __align__(8) ull mbar[2];

    const int tid = threadIdx.x;
    const int w = tid >> 5, lane = tid & 31;
    const int rowg = w & 7;                 // row group 0..7 (16 rows each)
    const int half = w >> 3;                // code half 0..1 (32 codes each)
    const int g = lane >> 2, tig = lane & 3;
    const int row0 = blockIdx.x * 128;
    const float* __restrict__ esq = g_esq[stage];
    const __half* __restrict__ PB = g_PB[stage];
    const uint32_t sb = (uint32_t)__cvta_generic_to_shared(smc);
    const uint32_t mb0 = (uint32_t)__cvta_generic_to_shared(&mbar[0]);
    const uint32_t mb1 = (uint32_t)__cvta_generic_to_shared(&mbar[1]);

    if (tid == 0) { mbar_init(mb0); mbar_init(mb1); }
    __syncthreads();

    // prefetch chunk 0 into buffer 0 (32KB = 64 codes)
    if (tid == 0) {
        mbar_expect(mb0, 32768u);
        bulk_cp(sb + P1_BOFF, PB, 32768u, mb0);
    }

    // fill persistent A planes (split ze into fp16 hi+lo)
#pragma unroll 4
    for (int i = 0; i < 16; i++) {
        int idx = tid + i * 512;
        int r = idx >> 6, c4 = idx & 63;
        float4 f = *(const float4*)(ze + (size_t)(row0 + r) * CDIM + c4 * 4);
        __half2 h01, h23, l01, l23;
        h01.x = __float2half(f.x); l01.x = __float2half(f.x - __half2float(h01.x));
        h01.y = __float2half(f.y); l01.y = __float2half(f.y - __half2float(h01.y));
        h23.x = __float2half(f.z); l23.x = __float2half(f.z - __half2float(h23.x));
        h23.y = __float2half(f.w); l23.y = __float2half(f.w - __half2float(h23.y));
        int o = r * P1_ASTR + c4 * 4;
        *(__half2*)(Ah + o) = h01; *(__half2*)(Ah + o + 2) = h23;
        *(__half2*)(Al + o) = l01; *(__half2*)(Al + o + 2) = l23;
    }

    float m1[2] = {3.4e38f, 3.4e38f}, m2[2] = {3.4e38f, 3.4e38f};
    int   i1[2] = {0, 0};

    // ldmatrix lane pointers (same fragment conventions as before)
    const uint32_t a_off =
        (uint32_t)(((rowg * 16 + (lane & 15)) * P1_ASTR + ((lane >> 4) << 3)) * 2);
    const uint32_t ah_base = sb + a_off;
    const uint32_t al_base = sb + 67584u + a_off;
    const uint32_t brow512 = (uint32_t)((((lane >> 4) << 3) + (lane & 7)) * 512);
    const int kb = (lane >> 3) & 1;
    const int bx = lane & 7;
    const uint32_t hoff = (uint32_t)half * 16384u;  // this warp's 32-code tile

    for (int t = 0; t < 64; t++) {
        mbar_wait((t & 1) ? mb1 : mb0, (t >> 1) & 1);
        __syncthreads();

        if (t < 63 && tid == 0) {
            const uint32_t dst = sb + P1_BOFF + ((t + 1) & 1) * 32768u;
            const uint32_t mb = ((t + 1) & 1) ? mb1 : mb0;
            mbar_expect(mb, 32768u);
            bulk_cp(dst, PB + (size_t)(t + 1) * 16384, 32768u, mb);
        }

        const uint32_t Bp = sb + P1_BOFF + (uint32_t)((t & 1) * 32768) + hoff;

        float acc[4][4];
#pragma unroll
        for (int nt = 0; nt < 4; nt++)
#pragma unroll
            for (int j = 0; j < 4; j++) acc[nt][j] = 0.f;

#pragma unroll 8
        for (int k = 0; k < 16; k++) {
            uint32_t ah[4], al[4];
            ldsm4(ah[0], ah[1], ah[2], ah[3], ah_base + (uint32_t)(k * 32));
            ldsm4(al[0], al[1], al[2], al[3], al_base + (uint32_t)(k * 32));

            const uint32_t blk = (uint32_t)((((k << 1) | kb) ^ bx) << 4);
            uint32_t b0[4], b1[4];
            ldsm4(b0[0], b0[1], b0[2], b0[3], Bp + brow512 + blk);
            ldsm4(b1[0], b1[1], b1[2], b1[3], Bp + 8192u + brow512 + blk);

            // ah * b (this warp's 32 codes)
            mma16816h(acc[0], ah, b0[0], b0[1]);
            mma16816h(acc[1], ah, b0[2], b0[3]);
            mma16816h(acc[2], ah, b1[0], b1[1]);
            mma16816h(acc[3], ah, b1[2], b1[3]);
            // al * b
            mma16816h(acc[0], al, b0[0], b0[1]);
            mma16816h(acc[1], al, b0[2], b0[3]);
            mma16816h(acc[2], al, b1[0], b1[1]);
            mma16816h(acc[3], al, b1[2], b1[3]);
        }

        // epilogue: per-thread min1/min2 over this warp's 32 codes
        const int code0 = t * 64 + half * 32;
#pragma unroll
        for (int nt = 0; nt < 4; nt++) {
            int c0 = code0 + nt * 8 + 2 * tig;
            float e0 = esq[c0], e1 = esq[c0 + 1];
#pragma unroll
            for (int s = 0; s < 2; s++) {       // s=0: row g, s=1: row g+8
                float d0 = fmaf(-2.f, acc[nt][s * 2 + 0], e0);
                if (d0 < m1[s]) { m2[s] = m1[s]; m1[s] = d0; i1[s] = c0; }
                else if (d0 < m2[s]) m2[s] = d0;
                float d1 = fmaf(-2.f, acc[nt][s * 2 + 1], e1);
                if (d1 < m1[s]) { m2[s] = m1[s]; m1[s] = d1; i1[s] = c0 + 1; }
                else if (d1 < m2[s]) m2[s] = d1;
            }
        }
    }

    // merge across the 4 tig lanes sharing each row (within this warp/half)
#pragma unroll
    for (int s = 0; s < 2; s++) {
#pragma unroll
        for (int off = 1; off <= 2; off <<= 1) {
            float o1 = __shfl_xor_sync(0xffffffffu, m1[s], off);
            int   oi = __shfl_xor_sync(0xffffffffu, i1[s], off);
            float o2 = __shfl_xor_sync(0xffffffffu, m2[s], off);
            float nm2 = fminf(fmaxf(m1[s], o1), fminf(m2[s], o2));
            if (o1 < m1[s] || (o1 == m1[s] && oi < i1[s])) { m1[s] = o1; i1[s] = oi; }
            m2[s] = nm2;
        }
    }

    // cross-half merge via smem (A region is dead now)
    float* mv1 = (float*)smc;            // [2][128]
    float* mv2 = (float*)(smc + 1024);   // [2][128]
    int*   mi1 = (int*)(smc + 2048);     // [2][128]
    __syncthreads();
    if (tig == 0) {
#pragma unroll
        for (int s = 0; s < 2; s++) {
            int rl = rowg * 16 + g + s * 8;
            mv1[half * 128 + rl] = m1[s];
            mv2[half * 128 + rl] = m2[s];
            mi1[half * 128 + rl] = i1[s];
        }
    }
    __syncthreads();
    if (tid < 128) {
        float v1a = mv1[tid], v2a = mv2[tid];
        float v1b = mv1[128 + tid], v2b = mv2[128 + tid];
        int ia = mi1[tid], ib = mi1[128 + tid];
        float bm1, bm2; int bi;
        if (v1a <= v1b) {                  // tie -> half0 (lower codes) first
            bm1 = v1a; bi = ia; bm2 = fminf(v2a, v1b);
        } else {
            bm1 = v1b; bi = ib; bm2 = fminf(v1a, v2b);
        }
        int row = row0 + tid;
        g_p1v1[row] = bm1;
        g_p1v2[row] = bm2;
        g_p1i1[row] = bi;
        g_fbkey[row] = ~0ull;
        if (bm2 - bm1 <= BAND) {
            int pos = atomicAdd(&g_fbcount[stage], 1);
            g_fbrows[pos] = row;
        }
    }
}

// ============================================================================
// PASS 2: exact fallback (exact reference arithmetic + atomicMin on monotone
// key -> exact argmin, lowest-index ties).
// ============================================================================
#define FB_SMEM ((256 * 68 + 32 * 132) * 4 + 256)

__global__ __launch_bounds__(256) void vq_fallback_kernel(
    const float* __restrict__ ze, const float* __restrict__ E, int stage)
{
    extern __shared__ __align__(16) float fsm[];
    float* As = fsm;
    float* Bs = fsm + 256 * 68;
    int* rowsm = (int*)(fsm + 256 * 68 + 32 * 132);

    const int cnt = g_fbcount[stage];
    const int tid = threadIdx.x, tx = tid & 15, ty = tid >> 4;
    const int seg0 = blockIdx.y * 512;
    const float* __restrict__ esq = g_esq[stage];

    for (int base = blockIdx.x * 64; base < cnt; base += gridDim.x * 64) {
        __syncthreads();
        if (tid < 64) rowsm[tid] = (base + tid < cnt) ? g_fbrows[base + tid] : -1;
        __syncthreads();
#pragma unroll 4
        for (int i = 0; i < 64; i++) {
            int idx = tid + i * 256;
            int r = idx >> 8, c = idx & 255;
            int rr = rowsm[r];
            As[c * 68 + r] = (rr >= 0) ? ze[(size_t)rr * CDIM + c] : 0.f;
        }
        float zrow[4]; int rid[4];
#pragma unroll
        for (int i = 0; i < 4; i++) {
            rid[i] = rowsm[ty * 4 + i];
            zrow[i] = (rid[i] >= 0) ? g_ze2[rid[i]] : 0.f;
        }
        float bestv[4]; int besti[4];
#pragma unroll
        for (int i = 0; i < 4; i++) { bestv[i] = 3.4e38f; besti[i] = 0; }
        __syncthreads();

        for (int cb = 0; cb < 512; cb += 128) {
            ull acc[4][4];
#pragma unroll
            for (int i = 0; i < 4; i++)
#pragma unroll
                for (int j = 0; j < 4; j++) acc[i][j] = 0ull;

            for (int c0 = 0; c0 < CDIM; c0 += 32) {
#pragma unroll
                for (int i = 0; i < 16; i++) {
                    int idx = tid + i * 256;
                    int code = idx >> 5, kk = idx & 31;
                    Bs[kk * 132 + code] =
                        E[(size_t)(seg0 + cb + code) * CDIM + c0 + kk];
                }
                __syncthreads();
#pragma unroll
                for (int kk = 0; kk < 32; kk++) {
                    const float* ar = As + (c0 + kk) * 68;
                    const float* br = Bs + kk * 132;
                    float4 a0 = *(const float4*)&ar[ty * 4];
                    ull aa[4] = {dup2(a0.x), dup2(a0.y), dup2(a0.z), dup2(a0.w)};
                    ulonglong2 b0 = *(const ulonglong2*)&br[tx * 4];
                    ulonglong2 b1 = *(const ulonglong2*)&br[64 + tx * 4];
                    ull bb[4] = {b0.x, b0.y, b1.x, b1.y};
#pragma unroll
                    for (int i = 0; i < 4; i++)
#pragma unroll
                        for (int j = 0; j < 4; j++) fma2(acc[i][j], aa[i], bb[j]);
                }
                __syncthreads();
            }
#pragma unroll
            for (int jh = 0; jh < 2; jh++) {
#pragma unroll
                for (int h = 0; h < 2; h++) {
                    int j2 = jh * 2 + h;
                    int col = seg0 + cb + jh * 64 + tx * 4 + h * 2;
                    float eq0 = esq[col], eq1 = esq[col + 1];
#pragma unroll
                    for (int i = 0; i < 4; i++) {
                        float2 pv = unpk2(acc[i][j2]);
                        float v0 = __fadd_rn(__fadd_rn(zrow[i], -__fmul_rn(2.f, pv.x)), eq0);
                        if (v0 < bestv[i]) { bestv[i] = v0; besti[i] = col; }
                        float v1 = __fadd_rn(__fadd_rn(zrow[i], -__fmul_rn(2.f, pv.y)), eq1);
                        if (v1 < bestv[i]) { bestv[i] = v1; besti[i] = col + 1; }
                    }
                }
            }
        }

#pragma unroll
        for (int i = 0; i < 4; i++) {
            float v = bestv[i]; int ix = besti[i];
#pragma unroll
            for (int off = 1; off <= 8; off <<= 1) {
                float ov = __shfl_xor_sync(0xffffffffu, v, off);
                int   oi = __shfl_xor_sync(0xffffffffu, ix, off);
                if (ov < v || (ov == v && oi < ix)) { v = ov; ix = oi; }
            }
            if (tx == 0 && rid[i] >= 0)
                atomicMin(&g_fbkey[rid[i]], dkey(v, ix));
        }
    }
}

// ============================================================================
// Gather: resolve nn; zq; residual; zq_sum; stage-3 straight-through;
// next-stage ||ze||^2 fused.
// ============================================================================
__global__ void gather_kernel(const float* __restrict__ ze,
                              const float* __restrict__ E,
                              float* __restrict__ zq_out,
                              float* __restrict__ ze_next,
                              float* __restrict__ nn_f,
                              const float* __restrict__ ze1,
                              int stage)
{
    __shared__ float buf[CDIM];
    int row = blockIdx.x, c = threadIdx.x;
    int idx = (g_p1v2[row] - g_p1v1[row] <= BAND)
                  ? (int)(unsigned)(g_fbkey[row] & 0xffffffffull)
                  : g_p1i1[row];

    float q = E[(size_t)idx * CDIM + c];
    size_t o = (size_t)row * CDIM + c;
    zq_out[o] = q;
    if (ze_next) {
        float zn = __fadd_rn(ze[o], -q);
        ze_next[o] = zn;
        buf[c] = zn;
    }
    float s = (stage == 0) ? q : __fadd_rn(g_zqsum[o], q);
    if (stage == 3) {
        float z1 = ze1[o];
        s = __fadd_rn(z1, __fadd_rn(s, -z1));
    }
    g_zqsum[o] = s;
    if (c == 0) nn_f[row] = (float)idx;

    if (ze_next) {
        __syncthreads();
        if (c == 0) {
            float acc = 0.f;
#pragma unroll 8
            for (int i = 0; i < CDIM; i++)
                acc = __fadd_rn(acc, __fmul_rn(buf[i], buf[i]));
            g_ze2[row] = acc;
        }
    }
}

// ============================================================================
// kernel_launch — output: x_hat | ze_1..4 | zq_1..4 | nn_1..4
// ============================================================================
extern "C" void kernel_launch(void* const* d_in, const int* in_sizes, int n_in,
                              void* d_out, int out_size)
{
    const float* x     = (const float*)d_in[0];
    const float* W_enc = (const float*)d_in[1];
    const float* b_enc = (const float*)d_in[2];
    const float* E[4]  = {(const float*)d_in[3], (const float*)d_in[4],
                          (const float*)d_in[5], (const float*)d_in[6]};
    const float* W_dec = (const float*)d_in[7];
    const float* b_dec = (const float*)d_in[8];

    float* out = (float*)d_out;
    const size_t NC     = (size_t)NROWS * CDIM;
    const size_t OFF_ZE = (size_t)NROWS * INDIM;
    const size_t OFF_ZQ = OFF_ZE + 4 * NC;
    const size_t OFF_NN = OFF_ZQ + 4 * NC;
    const float* ze1 = out + OFF_ZE;

    void* zqsum_ptr = nullptr;
    cudaGetSymbolAddress(&zqsum_ptr, g_zqsum);

    cudaFuncSetAttribute(vq_pass1_kernel,
                         cudaFuncAttributeMaxDynamicSharedMemorySize, P1_SMEM);
    cudaFuncSetAttribute(vq_fallback_kernel,
                         cudaFuncAttributeMaxDynamicSharedMemorySize, FB_SMEM);

    // one-time preprocessing
    esq4_kernel<<<dim3(KCODES / 32, 4), 256>>>(E[0], E[1], E[2], E[3]);
    pack_kernel<<<(4 * KCODES * 128) / 256, 256>>>(E[0], E[1], E[2], E[3]);

    // encoder
    sgemm_bias_kernel<<<dim3(CDIM / 128, NROWS / 128), 256>>>(
        x, W_enc, b_enc, out + OFF_ZE, NROWS, INDIM, CDIM);
    rownorm_kernel<<<NROWS / 32, 256>>>(out + OFF_ZE);

    // 4 sequential VQ stages
    for (int s = 0; s < 4; s++) {
        const float* zes = out + OFF_ZE + (size_t)s * NC;
        vq_pass1_kernel<<<NROWS / 128, 512, P1_SMEM>>>(zes, s);
        vq_fallback_kernel<<<dim3(32, 8), 256, FB_SMEM>>>(zes, E[s], s);
        float* zenext = (s < 3) ? (out + OFF_ZE + (size_t)(s + 1) * NC) : nullptr;
        gather_kernel<<<NROWS, 256>>>(zes, E[s],
                                      out + OFF_ZQ + (size_t)s * NC,
                                      zenext,
                                      out + OFF_NN + (size_t)s * NROWS,
                                      ze1, s);
    }

    // decoder
    sgemm_bias_kernel<<<dim3(INDIM / 128, NROWS / 128), 256>>>(
        (const float*)zqsum_ptr, W_dec, b_dec, out, NROWS, CDIM, INDIM);
}